// round 5
// baseline (speedup 1.0000x reference)
#include <cuda_runtime.h>
#include <cuda_bf16.h>
#include <math.h>

// Problem constants
#define BATCH 4
#define SEQ   2048
#define DMODEL 2048
#define NHEAD 16
#define HDIM  128
#define MROWS (BATCH * SEQ)          // 8192

// ---------------------------------------------------------------------------
// Scratch (device globals; no runtime allocation allowed)
// ---------------------------------------------------------------------------
__device__ float g_Q[(size_t)BATCH * NHEAD * SEQ * HDIM];     // [B,H,S,hd]
__device__ float g_K[(size_t)BATCH * NHEAD * SEQ * HDIM];
__device__ float g_V[(size_t)BATCH * NHEAD * SEQ * HDIM];
__device__ float g_ATT[(size_t)BATCH * SEQ * DMODEL];         // [B,S,H*hd]

// ---------------------------------------------------------------------------
// GEMM: out = A[MxK] * W[KxN] + bias[N]
// mode 0: out row-major [M,N]
// mode 1: out scattered to [B,H,S,hd] (m -> (b,s), n -> (h,t))
// Tiles: 128x128x8, 256 threads, 8x8 per-thread microtile, double-buffered.
// ---------------------------------------------------------------------------
__global__ __launch_bounds__(256) void gemm128(
    const float* __restrict__ A, const float* __restrict__ W,
    const float* __restrict__ bias, float* __restrict__ out,
    int M, int N, int K, int mode)
{
    __shared__ __align__(16) float As[2][8][128];
    __shared__ __align__(16) float Bs[2][8][128];

    const int tid = threadIdx.x;
    const int m0 = blockIdx.y * 128;
    const int n0 = blockIdx.x * 128;

    // global load assignments
    const int a_row  = tid >> 1;          // 0..127
    const int a_col4 = (tid & 1) * 4;     // 0 / 4
    const int b_row  = tid >> 5;          // 0..7
    const int b_col4 = (tid & 31) * 4;    // 0..124

    const float* Aptr = A + (size_t)(m0 + a_row) * K + a_col4;
    const float* Wptr = W + (size_t)b_row * N + n0 + b_col4;

    // stage 0
    float4 a4 = *(const float4*)Aptr;
    float4 b4 = *(const float4*)Wptr;
    As[0][a_col4 + 0][a_row] = a4.x;
    As[0][a_col4 + 1][a_row] = a4.y;
    As[0][a_col4 + 2][a_row] = a4.z;
    As[0][a_col4 + 3][a_row] = a4.w;
    *(float4*)&Bs[0][b_row][b_col4] = b4;
    __syncthreads();

    const int tx = tid & 15;              // col group
    const int ty = tid >> 4;              // row group

    float acc[8][8];
    #pragma unroll
    for (int i = 0; i < 8; i++)
        #pragma unroll
        for (int j = 0; j < 8; j++) acc[i][j] = 0.f;

    int buf = 0;
    for (int k0 = 0; k0 < K; k0 += 8) {
        const bool has_next = (k0 + 8) < K;
        if (has_next) {
            a4 = *(const float4*)(Aptr + k0 + 8);
            b4 = *(const float4*)(Wptr + (size_t)(k0 + 8) * N);
        }
        #pragma unroll
        for (int kk = 0; kk < 8; kk++) {
            float ra[8], rb[8];
            *(float4*)&ra[0] = *(const float4*)&As[buf][kk][ty * 4];
            *(float4*)&ra[4] = *(const float4*)&As[buf][kk][64 + ty * 4];
            *(float4*)&rb[0] = *(const float4*)&Bs[buf][kk][tx * 4];
            *(float4*)&rb[4] = *(const float4*)&Bs[buf][kk][64 + tx * 4];
            #pragma unroll
            for (int i = 0; i < 8; i++)
                #pragma unroll
                for (int j = 0; j < 8; j++)
                    acc[i][j] = fmaf(ra[i], rb[j], acc[i][j]);
        }
        if (has_next) {
            const int nb = buf ^ 1;
            As[nb][a_col4 + 0][a_row] = a4.x;
            As[nb][a_col4 + 1][a_row] = a4.y;
            As[nb][a_col4 + 2][a_row] = a4.z;
            As[nb][a_col4 + 3][a_row] = a4.w;
            *(float4*)&Bs[nb][b_row][b_col4] = b4;
        }
        __syncthreads();
        buf ^= 1;
    }

    // epilogue
    #pragma unroll
    for (int i = 0; i < 8; i++) {
        const int lr  = (i < 4) ? (ty * 4 + i) : (64 + ty * 4 + i - 4);
        const int row = m0 + lr;
        #pragma unroll
        for (int j = 0; j < 8; j++) {
            const int lc  = (j < 4) ? (tx * 4 + j) : (64 + tx * 4 + j - 4);
            const int col = n0 + lc;
            const float v = acc[i][j] + bias[col];
            if (mode == 0) {
                out[(size_t)row * N + col] = v;
            } else {
                const int b = row >> 11;          // / SEQ
                const int s = row & 2047;
                const int h = col >> 7;           // / HDIM
                const int t = col & 127;
                out[((((size_t)b * NHEAD + h) * SEQ) + s) * HDIM + t] = v;
            }
        }
    }
}

// ---------------------------------------------------------------------------
// Flash attention (fp32, online softmax). Br=Bc=64, hd=128.
// grid: (SEQ/64, B*H), 256 threads, dynamic smem ~117KB.
// ---------------------------------------------------------------------------
#define BR 64
#define BC 64
#define QP 132   // padded pitch for 128-wide fp32 tiles (float4-aligned, bank-spread)
#define PP 68    // padded pitch for 64-wide score tile

__global__ __launch_bounds__(256) void flash_kernel(
    const float* __restrict__ gQ, const float* __restrict__ gK,
    const float* __restrict__ gV, const int* __restrict__ mask,
    float* __restrict__ gO)
{
    extern __shared__ __align__(16) float sm[];
    float* Qs  = sm;                 // 64*132
    float* Ks  = Qs + BR * QP;       // 64*132
    float* Vs  = Ks + BC * QP;       // 64*132
    float* Ps  = Vs + BC * QP;       // 64*68
    float* m_s = Ps + BR * PP;       // 64
    float* l_s = m_s + BR;           // 64
    float* a_s = l_s + BR;           // 64

    const int tid = threadIdx.x;
    const int bh  = blockIdx.y;          // 0..63
    const int q0  = blockIdx.x * BR;
    const int b   = bh >> 4;
    const int h   = bh & 15;
    const float NEG_INF = __int_as_float(0xff800000);
    const float scale = 0.08838834764831845f;   // 128^-0.5

    // load Q tile (64 x 128)
    {
        const float* Qg = gQ + ((size_t)bh * SEQ + q0) * HDIM;
        for (int i = tid; i < BR * HDIM / 4; i += 256) {
            const int row = i >> 5;
            const int c4  = (i & 31) << 2;
            *(float4*)&Qs[row * QP + c4] = *(const float4*)(Qg + row * HDIM + c4);
        }
    }
    if (tid < BR) { m_s[tid] = NEG_INF; l_s[tid] = 0.f; }

    const int sy = tid >> 4;   // row group (4 rows) for S; also O rows
    const int sx = tid & 15;   // col group: 4 cols for S, 8 cols for O

    float acc[4][8];
    #pragma unroll
    for (int r = 0; r < 4; r++)
        #pragma unroll
        for (int c = 0; c < 8; c++) acc[r][c] = 0.f;

    for (int kt = 0; kt < SEQ / BC; kt++) {
        const int kbase = kt * BC;
        // load K,V tiles
        {
            const float* Kg = gK + ((size_t)bh * SEQ + kbase) * HDIM;
            const float* Vg = gV + ((size_t)bh * SEQ + kbase) * HDIM;
            for (int i = tid; i < BC * HDIM / 4; i += 256) {
                const int row = i >> 5;
                const int c4  = (i & 31) << 2;
                *(float4*)&Ks[row * QP + c4] = *(const float4*)(Kg + row * HDIM + c4);
                *(float4*)&Vs[row * QP + c4] = *(const float4*)(Vg + row * HDIM + c4);
            }
        }
        __syncthreads();

        // S tile = Q K^T (each thread: 4x4)
        float s_acc[4][4];
        #pragma unroll
        for (int i = 0; i < 4; i++)
            #pragma unroll
            for (int j = 0; j < 4; j++) s_acc[i][j] = 0.f;

        #pragma unroll 4
        for (int t4 = 0; t4 < HDIM / 4; t4++) {
            float4 qv[4], kv[4];
            #pragma unroll
            for (int i = 0; i < 4; i++)
                qv[i] = *(const float4*)&Qs[(sy * 4 + i) * QP + t4 * 4];
            #pragma unroll
            for (int j = 0; j < 4; j++)
                kv[j] = *(const float4*)&Ks[(sx * 4 + j) * QP + t4 * 4];
            #pragma unroll
            for (int i = 0; i < 4; i++)
                #pragma unroll
                for (int j = 0; j < 4; j++) {
                    s_acc[i][j] = fmaf(qv[i].x, kv[j].x, s_acc[i][j]);
                    s_acc[i][j] = fmaf(qv[i].y, kv[j].y, s_acc[i][j]);
                    s_acc[i][j] = fmaf(qv[i].z, kv[j].z, s_acc[i][j]);
                    s_acc[i][j] = fmaf(qv[i].w, kv[j].w, s_acc[i][j]);
                }
        }

        // scale + mask + write to Ps
        #pragma unroll
        for (int i = 0; i < 4; i++) {
            const int r = sy * 4 + i;
            const size_t mrow = ((size_t)b * SEQ + (q0 + r)) * SEQ + kbase;
            #pragma unroll
            for (int j = 0; j < 4; j++) {
                const int c = sx * 4 + j;
                float v = s_acc[i][j] * scale;
                if (mask[mrow + c] == 0) v = NEG_INF;
                Ps[r * PP + c] = v;
            }
        }
        __syncthreads();

        // online softmax row pass (64 threads, one per row)
        if (tid < BR) {
            const int r = tid;
            const float mo = m_s[r];
            float mx = mo;
            #pragma unroll 8
            for (int j = 0; j < BC; j++) mx = fmaxf(mx, Ps[r * PP + j]);
            const float al = __expf(mo - mx);
            float sum = 0.f;
            #pragma unroll 8
            for (int j = 0; j < BC; j++) {
                const float e = __expf(Ps[r * PP + j] - mx);
                Ps[r * PP + j] = e;
                sum += e;
            }
            m_s[r] = mx;
            l_s[r] = l_s[r] * al + sum;
            a_s[r] = al;
        }
        __syncthreads();

        // O = O*alpha + P @ V  (each thread: 4 rows x 8 cols)
        float alr[4];
        #pragma unroll
        for (int r = 0; r < 4; r++) alr[r] = a_s[sy * 4 + r];
        #pragma unroll
        for (int r = 0; r < 4; r++)
            #pragma unroll
            for (int c = 0; c < 8; c++) acc[r][c] *= alr[r];

        #pragma unroll 4
        for (int j = 0; j < BC; j++) {
            const float4 v0 = *(const float4*)&Vs[j * QP + sx * 8];
            const float4 v1 = *(const float4*)&Vs[j * QP + sx * 8 + 4];
            float p[4];
            #pragma unroll
            for (int r = 0; r < 4; r++) p[r] = Ps[(sy * 4 + r) * PP + j];
            #pragma unroll
            for (int r = 0; r < 4; r++) {
                acc[r][0] = fmaf(p[r], v0.x, acc[r][0]);
                acc[r][1] = fmaf(p[r], v0.y, acc[r][1]);
                acc[r][2] = fmaf(p[r], v0.z, acc[r][2]);
                acc[r][3] = fmaf(p[r], v0.w, acc[r][3]);
                acc[r][4] = fmaf(p[r], v1.x, acc[r][4]);
                acc[r][5] = fmaf(p[r], v1.y, acc[r][5]);
                acc[r][6] = fmaf(p[r], v1.z, acc[r][6]);
                acc[r][7] = fmaf(p[r], v1.w, acc[r][7]);
            }
        }
        __syncthreads();
    }

    // normalize and write out in [B, S, H*hd] layout
    #pragma unroll
    for (int r = 0; r < 4; r++) {
        const int row = sy * 4 + r;
        const float inv = 1.f / l_s[row];
        const int s = q0 + row;
        float* op = gO + ((((size_t)b * SEQ + s) * NHEAD) + h) * HDIM + sx * 8;
        #pragma unroll
        for (int c = 0; c < 8; c++) op[c] = acc[r][c] * inv;
    }
}

// ---------------------------------------------------------------------------
// Launch
// ---------------------------------------------------------------------------
extern "C" void kernel_launch(void* const* d_in, const int* in_sizes, int n_in,
                              void* d_out, int out_size)
{
    const float* x    = (const float*)d_in[0];
    const int*   mask = (const int*)  d_in[1];
    const float* Wq   = (const float*)d_in[2];
    const float* bq   = (const float*)d_in[3];
    const float* Wk   = (const float*)d_in[4];
    const float* bk   = (const float*)d_in[5];
    const float* Wv   = (const float*)d_in[6];
    const float* bv   = (const float*)d_in[7];
    const float* Wo   = (const float*)d_in[8];
    const float* bo   = (const float*)d_in[9];
    float* out = (float*)d_out;

    float *pQ, *pK, *pV, *pA;
    cudaGetSymbolAddress((void**)&pQ, g_Q);
    cudaGetSymbolAddress((void**)&pK, g_K);
    cudaGetSymbolAddress((void**)&pV, g_V);
    cudaGetSymbolAddress((void**)&pA, g_ATT);

    const dim3 tpb(256);
    const dim3 gproj(DMODEL / 128, MROWS / 128);   // (16, 64)

    gemm128<<<gproj, tpb>>>(x, Wq, bq, pQ, MROWS, DMODEL, DMODEL, 1);
    gemm128<<<gproj, tpb>>>(x, Wk, bk, pK, MROWS, DMODEL, DMODEL, 1);
    gemm128<<<gproj, tpb>>>(x, Wv, bv, pV, MROWS, DMODEL, DMODEL, 1);

    const size_t shmem = (size_t)(3 * BR * QP + BR * PP + 3 * BR) * sizeof(float); // 119552
    cudaFuncSetAttribute(flash_kernel, cudaFuncAttributeMaxDynamicSharedMemorySize, (int)shmem);
    flash_kernel<<<dim3(SEQ / BR, BATCH * NHEAD), tpb, shmem>>>(pQ, pK, pV, mask, pA);

    gemm128<<<gproj, tpb>>>(pA, Wo, bo, out, MROWS, DMODEL, DMODEL, 0);
}

// round 7
// speedup vs baseline: 2.5926x; 2.5926x over previous
#include <cuda_runtime.h>
#include <cuda_bf16.h>
#include <math.h>
#include <stdint.h>

#define BATCH  4
#define SEQ    2048
#define DMODEL 2048
#define NHEAD  16
#define HDIM   128
#define MROWS  (BATCH * SEQ)   // 8192

typedef __nv_bfloat16 bf16;

// ---------------------------------------------------------------------------
// Scratch (device globals; no runtime allocation allowed)
// ---------------------------------------------------------------------------
__device__ bf16 g_xh[(size_t)MROWS * DMODEL];
__device__ bf16 g_xl[(size_t)MROWS * DMODEL];
__device__ bf16 g_Wh[(size_t)DMODEL * DMODEL];
__device__ bf16 g_Wl[(size_t)DMODEL * DMODEL];
__device__ bf16 g_Qh[(size_t)MROWS * DMODEL];
__device__ bf16 g_Ql[(size_t)MROWS * DMODEL];
__device__ bf16 g_Kh[(size_t)MROWS * DMODEL];
__device__ bf16 g_Kl[(size_t)MROWS * DMODEL];
__device__ bf16 g_Vh[(size_t)MROWS * DMODEL];
__device__ bf16 g_Vl[(size_t)MROWS * DMODEL];
__device__ bf16 g_Ah[(size_t)MROWS * DMODEL];
__device__ bf16 g_Al[(size_t)MROWS * DMODEL];

// ---------------------------------------------------------------------------
// Helpers
// ---------------------------------------------------------------------------
__device__ __forceinline__ void ldsm_x4(uint32_t r[4], const void* p) {
    uint32_t a = (uint32_t)__cvta_generic_to_shared(p);
    asm volatile("ldmatrix.sync.aligned.m8n8.x4.shared.b16 {%0,%1,%2,%3}, [%4];"
                 : "=r"(r[0]), "=r"(r[1]), "=r"(r[2]), "=r"(r[3]) : "r"(a));
}
__device__ __forceinline__ void ldsm_x4t(uint32_t r[4], const void* p) {
    uint32_t a = (uint32_t)__cvta_generic_to_shared(p);
    asm volatile("ldmatrix.sync.aligned.m8n8.x4.trans.shared.b16 {%0,%1,%2,%3}, [%4];"
                 : "=r"(r[0]), "=r"(r[1]), "=r"(r[2]), "=r"(r[3]) : "r"(a));
}
__device__ __forceinline__ void mma_bf16(float c[4], const uint32_t a[4], const uint32_t b[2]) {
    asm volatile(
        "mma.sync.aligned.m16n8k16.row.col.f32.bf16.bf16.f32 "
        "{%0,%1,%2,%3}, {%4,%5,%6,%7}, {%8,%9}, {%0,%1,%2,%3};"
        : "+f"(c[0]), "+f"(c[1]), "+f"(c[2]), "+f"(c[3])
        : "r"(a[0]), "r"(a[1]), "r"(a[2]), "r"(a[3]), "r"(b[0]), "r"(b[1]));
}
__device__ __forceinline__ void cp16(void* s, const void* g) {
    uint32_t sa = (uint32_t)__cvta_generic_to_shared(s);
    asm volatile("cp.async.cg.shared.global [%0], [%1], 16;" :: "r"(sa), "l"(g));
}
__device__ __forceinline__ void cp_commit() { asm volatile("cp.async.commit_group;"); }
__device__ __forceinline__ void cp_wait0()  { asm volatile("cp.async.wait_group 0;"); }

// ---------------------------------------------------------------------------
// Split fp32 -> (bf16 hi, bf16 lo)
// ---------------------------------------------------------------------------
__global__ __launch_bounds__(256) void split_kernel(
    const float* __restrict__ in, bf16* __restrict__ hi, bf16* __restrict__ lo, int n4)
{
    int i = blockIdx.x * 256 + threadIdx.x;
    if (i >= n4) return;
    float4 f = ((const float4*)in)[i];
    bf16 h0 = __float2bfloat16(f.x); bf16 l0 = __float2bfloat16(f.x - __bfloat162float(h0));
    bf16 h1 = __float2bfloat16(f.y); bf16 l1 = __float2bfloat16(f.y - __bfloat162float(h1));
    bf16 h2 = __float2bfloat16(f.z); bf16 l2 = __float2bfloat16(f.z - __bfloat162float(h2));
    bf16 h3 = __float2bfloat16(f.w); bf16 l3 = __float2bfloat16(f.w - __bfloat162float(h3));
    __nv_bfloat162 a, b;
    a.x = h0; a.y = h1; b.x = h2; b.y = h3;
    ((__nv_bfloat162*)hi)[2 * i] = a; ((__nv_bfloat162*)hi)[2 * i + 1] = b;
    a.x = l0; a.y = l1; b.x = l2; b.y = l3;
    ((__nv_bfloat162*)lo)[2 * i] = a; ((__nv_bfloat162*)lo)[2 * i + 1] = b;
}

// ---------------------------------------------------------------------------
// GEMM bf16x3: C = Ah*Bh + Ah*Bl + Al*Bh + bias  (fp32 accumulation)
// A [M,K] row-major hi/lo, B [K,N] row-major hi/lo.
// mode 0: write Ch/Cl [M,N] bf16 hi/lo
// mode 1: scatter Ch/Cl to [B,H,S,hd]
// mode 2: write Cf fp32 [M,N]
// Tiles 128x128x32, 256 threads (8 warps, each 32m x 64n), cp.async dbuf.
// ---------------------------------------------------------------------------
#define GBK 32
#define AP  40    // halves pitch of A smem tile (32 + 8)
#define BP  136   // halves pitch of B smem tile (128 + 8)
#define A_ST (128 * AP * 2)   // 10240 B
#define B_ST (GBK * BP * 2)   // 8704 B
#define GSM_AH 0
#define GSM_AL (2 * A_ST)
#define GSM_BH (4 * A_ST)
#define GSM_BL (4 * A_ST + 2 * B_ST)
#define GSMEM  (4 * A_ST + 4 * B_ST)   // 75776 B

__global__ __launch_bounds__(256) void gemm_bf16x3(
    const bf16* __restrict__ Agh, const bf16* __restrict__ Agl,
    const bf16* __restrict__ Bgh, const bf16* __restrict__ Bgl,
    const float* __restrict__ bias,
    bf16* __restrict__ Ch, bf16* __restrict__ Cl, float* __restrict__ Cf,
    int M, int N, int K, int mode)
{
    extern __shared__ char sm[];
    const int tid = threadIdx.x;
    const int l   = tid & 31;
    const int wid = tid >> 5;
    const int wm  = (wid & 3) * 32;     // warp row base within tile
    const int wn  = (wid >> 2) * 64;    // warp col base within tile
    const int m0  = blockIdx.y * 128;
    const int n0  = blockIdx.x * 128;

    float acc[2][8][4];
    #pragma unroll
    for (int mt = 0; mt < 2; mt++)
        #pragma unroll
        for (int nt = 0; nt < 8; nt++)
            #pragma unroll
            for (int q = 0; q < 4; q++) acc[mt][nt][q] = 0.f;

    // stage-issue lambda (8 cp.async of 16B per thread)
    auto issue = [&](int k0, int st) {
        char* pAh = sm + GSM_AH + st * A_ST;
        char* pAl = sm + GSM_AL + st * A_ST;
        char* pBh = sm + GSM_BH + st * B_ST;
        char* pBl = sm + GSM_BL + st * B_ST;
        #pragma unroll
        for (int j = 0; j < 2; j++) {
            int u  = tid + j * 256;
            int r  = u >> 2;              // 0..127
            int c8 = (u & 3) * 8;         // 0..24
            size_t ga = (size_t)(m0 + r) * K + k0 + c8;
            cp16(pAh + (r * AP + c8) * 2, Agh + ga);
            cp16(pAl + (r * AP + c8) * 2, Agl + ga);
            int rb  = u >> 4;             // 0..31
            int cb8 = (u & 15) * 8;       // 0..120
            size_t gb = (size_t)(k0 + rb) * N + n0 + cb8;
            cp16(pBh + (rb * BP + cb8) * 2, Bgh + gb);
            cp16(pBl + (rb * BP + cb8) * 2, Bgl + gb);
        }
    };

    issue(0, 0); cp_commit(); cp_wait0(); __syncthreads();

    int st = 0;
    for (int k0 = 0; k0 < K; k0 += GBK) {
        const bool nxt = (k0 + GBK) < K;
        if (nxt) { issue(k0 + GBK, st ^ 1); cp_commit(); }

        char* pAh = sm + GSM_AH + st * A_ST;
        char* pAl = sm + GSM_AL + st * A_ST;
        char* pBh = sm + GSM_BH + st * B_ST;
        char* pBl = sm + GSM_BL + st * B_ST;

        #pragma unroll
        for (int ks = 0; ks < 2; ks++) {
            uint32_t ah[2][4], al[2][4];
            #pragma unroll
            for (int mt = 0; mt < 2; mt++) {
                int off = ((wm + mt * 16 + (l & 15)) * AP + ks * 16 + ((l & 16) >> 1)) * 2;
                ldsm_x4(ah[mt], pAh + off);
                ldsm_x4(al[mt], pAl + off);
            }
            uint32_t bh[4][4], bl[4][4];
            #pragma unroll
            for (int q = 0; q < 4; q++) {
                int off = ((ks * 16 + (l & 15)) * BP + wn + q * 16 + ((l & 16) >> 1)) * 2;
                ldsm_x4t(bh[q], pBh + off);
                ldsm_x4t(bl[q], pBl + off);
            }
            #pragma unroll
            for (int mt = 0; mt < 2; mt++)
                #pragma unroll
                for (int nt = 0; nt < 8; nt++) {
                    const uint32_t* bhp = &bh[nt >> 1][(nt & 1) * 2];
                    const uint32_t* blp = &bl[nt >> 1][(nt & 1) * 2];
                    mma_bf16(acc[mt][nt], ah[mt], bhp);
                    mma_bf16(acc[mt][nt], ah[mt], blp);
                    mma_bf16(acc[mt][nt], al[mt], bhp);
                }
        }
        if (nxt) cp_wait0();
        __syncthreads();
        st ^= 1;
    }

    // epilogue
    #pragma unroll
    for (int mt = 0; mt < 2; mt++) {
        #pragma unroll
        for (int nt = 0; nt < 8; nt++) {
            int r0 = m0 + wm + mt * 16 + (l >> 2);
            int c  = n0 + wn + nt * 8 + (l & 3) * 2;
            float v[4];
            v[0] = acc[mt][nt][0] + bias[c];
            v[1] = acc[mt][nt][1] + bias[c + 1];
            v[2] = acc[mt][nt][2] + bias[c];
            v[3] = acc[mt][nt][3] + bias[c + 1];
            #pragma unroll
            for (int e = 0; e < 4; e++) {
                int row = r0 + (e >> 1) * 8;
                int col = c + (e & 1);
                if (mode == 2) {
                    Cf[(size_t)row * N + col] = v[e];
                } else {
                    size_t idx;
                    if (mode == 0) idx = (size_t)row * N + col;
                    else {
                        int b = row >> 11, s = row & 2047;
                        int h = col >> 7,  t = col & 127;
                        idx = ((((size_t)b * NHEAD + h) * SEQ) + s) * HDIM + t;
                    }
                    bf16 hh = __float2bfloat16(v[e]);
                    Ch[idx] = hh;
                    Cl[idx] = __float2bfloat16(v[e] - __bfloat162float(hh));
                }
            }
        }
    }
}

// ---------------------------------------------------------------------------
// Flash attention bf16x3 tensor-core. Br=Bc=64, hd=128, 256 threads (8 warps).
// S = Q K^T via mma -> fp32 smem -> row softmax -> P hi/lo smem -> P V via mma.
// Writes attention output directly as hi/lo bf16 in [B,S,D] layout.
// ---------------------------------------------------------------------------
#define FP  136   // half pitch, 128-wide tiles (Q/K/V)
#define SSP 65    // float pitch, S tile
#define PHP 72    // half pitch, P tile (64-wide)

#define F_QH 0
#define F_QL (F_QH + 64 * FP * 2)       // 17408 each
#define F_KH (F_QL + 64 * FP * 2)
#define F_KL (F_KH + 64 * FP * 2)
#define F_VH (F_KL + 64 * FP * 2)
#define F_VL (F_VH + 64 * FP * 2)
#define F_SS (F_VL + 64 * FP * 2)       // 64*65*4 = 16640
#define F_PH (F_SS + 64 * SSP * 4)
#define F_PL (F_PH + 64 * PHP * 2)      // 9216 each
#define F_M  (F_PL + 64 * PHP * 2)
#define F_L  (F_M + 256)
#define F_A  (F_L + 256)
#define FSMEM (F_A + 256)               // 140288 B

__global__ __launch_bounds__(256) void flash_bf16(
    const bf16* __restrict__ Qh, const bf16* __restrict__ Ql,
    const bf16* __restrict__ Kh, const bf16* __restrict__ Kl,
    const bf16* __restrict__ Vh, const bf16* __restrict__ Vl,
    const int* __restrict__ mask,
    bf16* __restrict__ Oh, bf16* __restrict__ Ol)
{
    extern __shared__ char sm[];
    const int tid = threadIdx.x;
    const int l   = tid & 31;
    const int wid = tid >> 5;
    const int wm  = (wid & 3) * 16;     // warp row base (0..48)
    const int wsn = (wid >> 2);         // 0/1
    const int bh  = blockIdx.y;
    const int q0  = blockIdx.x * 64;
    const int b   = bh >> 4;
    const int h   = bh & 15;
    const float NEG_INF = __int_as_float(0xff800000);
    const float SCALE = 0.08838834764831845f;

    float* sS = (float*)(sm + F_SS);
    float* sM = (float*)(sm + F_M);
    float* sL = (float*)(sm + F_L);
    float* sA = (float*)(sm + F_A);
    bf16*  sPh = (bf16*)(sm + F_PH);
    bf16*  sPl = (bf16*)(sm + F_PL);

    // load Q tile (hi/lo)
    {
        const size_t qb = ((size_t)bh * SEQ + q0) * HDIM;
        #pragma unroll
        for (int j = 0; j < 4; j++) {
            int u = tid + j * 256;
            int r = u >> 4, c8 = (u & 15) * 8;
            *(uint4*)(sm + F_QH + (r * FP + c8) * 2) = *(const uint4*)(Qh + qb + (size_t)r * HDIM + c8);
            *(uint4*)(sm + F_QL + (r * FP + c8) * 2) = *(const uint4*)(Ql + qb + (size_t)r * HDIM + c8);
        }
    }
    if (tid < 64) { sM[tid] = NEG_INF; sL[tid] = 0.f; }

    float oacc[8][4];
    #pragma unroll
    for (int nt = 0; nt < 8; nt++)
        #pragma unroll
        for (int q = 0; q < 4; q++) oacc[nt][q] = 0.f;

    for (int kt = 0; kt < SEQ / 64; kt++) {
        const int kbase = kt * 64;
        __syncthreads();   // Q/P/V from previous iter fully consumed

        // load K,V tiles (hi/lo)
        {
            const size_t kb = ((size_t)bh * SEQ + kbase) * HDIM;
            #pragma unroll
            for (int j = 0; j < 4; j++) {
                int u = tid + j * 256;
                int r = u >> 4, c8 = (u & 15) * 8;
                size_t g = kb + (size_t)r * HDIM + c8;
                int so = (r * FP + c8) * 2;
                *(uint4*)(sm + F_KH + so) = *(const uint4*)(Kh + g);
                *(uint4*)(sm + F_KL + so) = *(const uint4*)(Kl + g);
                *(uint4*)(sm + F_VH + so) = *(const uint4*)(Vh + g);
                *(uint4*)(sm + F_VL + so) = *(const uint4*)(Vl + g);
            }
        }
        __syncthreads();

        // ---- S = Q K^T (bf16x3) : warp tile 16m x 32n ----
        float sacc[4][4];
        #pragma unroll
        for (int nt = 0; nt < 4; nt++)
            #pragma unroll
            for (int q = 0; q < 4; q++) sacc[nt][q] = 0.f;

        #pragma unroll
        for (int ks = 0; ks < 8; ks++) {
            uint32_t qh4[4], ql4[4];
            int qoff = ((wm + (l & 15)) * FP + ks * 16 + ((l & 16) >> 1)) * 2;
            ldsm_x4(qh4, sm + F_QH + qoff);
            ldsm_x4(ql4, sm + F_QL + qoff);
            uint32_t kh4[2][4], kl4[2][4];
            #pragma unroll
            for (int q = 0; q < 2; q++) {
                int nr = wsn * 32 + q * 16 + (l & 7) + ((l & 16) >> 1);
                int kc = ks * 16 + (l & 8);
                int off = (nr * FP + kc) * 2;
                ldsm_x4(kh4[q], sm + F_KH + off);
                ldsm_x4(kl4[q], sm + F_KL + off);
            }
            #pragma unroll
            for (int nt = 0; nt < 4; nt++) {
                const uint32_t* bhp = &kh4[nt >> 1][(nt & 1) * 2];
                const uint32_t* blp = &kl4[nt >> 1][(nt & 1) * 2];
                mma_bf16(sacc[nt], qh4, bhp);
                mma_bf16(sacc[nt], qh4, blp);
                mma_bf16(sacc[nt], ql4, bhp);
            }
        }
        // store S * scale
        #pragma unroll
        for (int nt = 0; nt < 4; nt++) {
            int r = wm + (l >> 2);
            int c = wsn * 32 + nt * 8 + (l & 3) * 2;
            sS[r * SSP + c]           = sacc[nt][0] * SCALE;
            sS[r * SSP + c + 1]       = sacc[nt][1] * SCALE;
            sS[(r + 8) * SSP + c]     = sacc[nt][2] * SCALE;
            sS[(r + 8) * SSP + c + 1] = sacc[nt][3] * SCALE;
        }
        __syncthreads();

        // ---- online softmax: 4 threads per row, 16 cols each ----
        {
            int r  = tid >> 2;
            int qd = tid & 3;
            const int* mrow = mask + ((size_t)b * SEQ + q0 + r) * SEQ + kbase + qd * 16;
            float vals[16];
            float mx = NEG_INF;
            #pragma unroll
            for (int j = 0; j < 16; j++) {
                float v = sS[r * SSP + qd * 16 + j];
                if (mrow[j] == 0) v = NEG_INF;
                vals[j] = v;
                mx = fmaxf(mx, v);
            }
            mx = fmaxf(mx, __shfl_xor_sync(0xffffffffu, mx, 1));
            mx = fmaxf(mx, __shfl_xor_sync(0xffffffffu, mx, 2));
            float mo = sM[r];
            float mn = fmaxf(mo, mx);
            float sum = 0.f;
            #pragma unroll
            for (int j = 0; j < 16; j++) {
                float e = __expf(vals[j] - mn);
                sum += e;
                bf16 eh = __float2bfloat16(e);
                sPh[r * PHP + qd * 16 + j] = eh;
                sPl[r * PHP + qd * 16 + j] = __float2bfloat16(e - __bfloat162float(eh));
            }
            sum += __shfl_xor_sync(0xffffffffu, sum, 1);
            sum += __shfl_xor_sync(0xffffffffu, sum, 2);
            if (qd == 0) {
                float al = __expf(mo - mn);
                sM[r] = mn;
                sL[r] = sL[r] * al + sum;
                sA[r] = al;
            }
        }
        __syncthreads();

        // ---- rescale O, then O += P V (bf16x3) : warp tile 16m x 64n ----
        {
            float a0 = sA[wm + (l >> 2)];
            float a1 = sA[wm + (l >> 2) + 8];
            #pragma unroll
            for (int nt = 0; nt < 8; nt++) {
                oacc[nt][0] *= a0; oacc[nt][1] *= a0;
                oacc[nt][2] *= a1; oacc[nt][3] *= a1;
            }
        }
        #pragma unroll
        for (int ks = 0; ks < 4; ks++) {
            uint32_t ph4[4], pl4[4];
            int poff = ((wm + (l & 15)) * PHP + ks * 16 + ((l & 16) >> 1)) * 2;
            ldsm_x4(ph4, sm + F_PH + poff);
            ldsm_x4(pl4, sm + F_PL + poff);
            uint32_t vh4[4][4], vl4[4][4];
            #pragma unroll
            for (int q = 0; q < 4; q++) {
                int vr = ks * 16 + (l & 15);
                int vc = wsn * 64 + q * 16 + ((l & 16) >> 1);
                int off = (vr * FP + vc) * 2;
                ldsm_x4t(vh4[q], sm + F_VH + off);
                ldsm_x4t(vl4[q], sm + F_VL + off);
            }
            #pragma unroll
            for (int nt = 0; nt < 8; nt++) {
                const uint32_t* bhp = &vh4[nt >> 1][(nt & 1) * 2];
                const uint32_t* blp = &vl4[nt >> 1][(nt & 1) * 2];
                mma_bf16(oacc[nt], ph4, bhp);
                mma_bf16(oacc[nt], ph4, blp);
                mma_bf16(oacc[nt], pl4, bhp);
            }
        }
    }
    __syncthreads();

    // epilogue: normalize, write hi/lo to [B,S,D] layout
    {
        int r0 = wm + (l >> 2);
        float inv0 = 1.f / sL[r0];
        float inv1 = 1.f / sL[r0 + 8];
        #pragma unroll
        for (int nt = 0; nt < 8; nt++) {
            int c = wsn * 64 + nt * 8 + (l & 3) * 2;
            size_t i0 = ((size_t)(b * SEQ + q0 + r0)) * DMODEL + h * HDIM + c;
            size_t i1 = ((size_t)(b * SEQ + q0 + r0 + 8)) * DMODEL + h * HDIM + c;
            float v00 = oacc[nt][0] * inv0, v01 = oacc[nt][1] * inv0;
            float v10 = oacc[nt][2] * inv1, v11 = oacc[nt][3] * inv1;
            bf16 hh;
            hh = __float2bfloat16(v00); Oh[i0]     = hh; Ol[i0]     = __float2bfloat16(v00 - __bfloat162float(hh));
            hh = __float2bfloat16(v01); Oh[i0 + 1] = hh; Ol[i0 + 1] = __float2bfloat16(v01 - __bfloat162float(hh));
            hh = __float2bfloat16(v10); Oh[i1]     = hh; Ol[i1]     = __float2bfloat16(v10 - __bfloat162float(hh));
            hh = __float2bfloat16(v11); Oh[i1 + 1] = hh; Ol[i1 + 1] = __float2bfloat16(v11 - __bfloat162float(hh));
        }
    }
}

// ---------------------------------------------------------------------------
// Launch
// ---------------------------------------------------------------------------
extern "C" void kernel_launch(void* const* d_in, const int* in_sizes, int n_in,
                              void* d_out, int out_size)
{
    const float* x    = (const float*)d_in[0];
    const int*   mask = (const int*)  d_in[1];
    const float* Wq   = (const float*)d_in[2];
    const float* bq   = (const float*)d_in[3];
    const float* Wk   = (const float*)d_in[4];
    const float* bk   = (const float*)d_in[5];
    const float* Wv   = (const float*)d_in[6];
    const float* bv   = (const float*)d_in[7];
    const float* Wo   = (const float*)d_in[8];
    const float* bo   = (const float*)d_in[9];
    float* out = (float*)d_out;

    bf16 *pxh, *pxl, *pWh, *pWl, *pQh, *pQl, *pKh, *pKl, *pVh, *pVl, *pAh, *pAl;
    cudaGetSymbolAddress((void**)&pxh, g_xh);
    cudaGetSymbolAddress((void**)&pxl, g_xl);
    cudaGetSymbolAddress((void**)&pWh, g_Wh);
    cudaGetSymbolAddress((void**)&pWl, g_Wl);
    cudaGetSymbolAddress((void**)&pQh, g_Qh);
    cudaGetSymbolAddress((void**)&pQl, g_Ql);
    cudaGetSymbolAddress((void**)&pKh, g_Kh);
    cudaGetSymbolAddress((void**)&pKl, g_Kl);
    cudaGetSymbolAddress((void**)&pVh, g_Vh);
    cudaGetSymbolAddress((void**)&pVl, g_Vl);
    cudaGetSymbolAddress((void**)&pAh, g_Ah);
    cudaGetSymbolAddress((void**)&pAl, g_Al);

    cudaFuncSetAttribute(gemm_bf16x3, cudaFuncAttributeMaxDynamicSharedMemorySize, GSMEM);
    cudaFuncSetAttribute(flash_bf16, cudaFuncAttributeMaxDynamicSharedMemorySize, FSMEM);

    const int n4x = MROWS * DMODEL / 4;
    const int n4w = DMODEL * DMODEL / 4;
    const dim3 gg(DMODEL / 128, MROWS / 128);   // (16, 64)

    split_kernel<<<(n4x + 255) / 256, 256>>>(x, pxh, pxl, n4x);

    split_kernel<<<(n4w + 255) / 256, 256>>>(Wq, pWh, pWl, n4w);
    gemm_bf16x3<<<gg, 256, GSMEM>>>(pxh, pxl, pWh, pWl, bq, pQh, pQl, nullptr,
                                    MROWS, DMODEL, DMODEL, 1);
    split_kernel<<<(n4w + 255) / 256, 256>>>(Wk, pWh, pWl, n4w);
    gemm_bf16x3<<<gg, 256, GSMEM>>>(pxh, pxl, pWh, pWl, bk, pKh, pKl, nullptr,
                                    MROWS, DMODEL, DMODEL, 1);
    split_kernel<<<(n4w + 255) / 256, 256>>>(Wv, pWh, pWl, n4w);
    gemm_bf16x3<<<gg, 256, GSMEM>>>(pxh, pxl, pWh, pWl, bv, pVh, pVl, nullptr,
                                    MROWS, DMODEL, DMODEL, 1);

    flash_bf16<<<dim3(SEQ / 64, BATCH * NHEAD), 256, FSMEM>>>(
        pQh, pQl, pKh, pKl, pVh, pVl, mask, pAh, pAl);

    split_kernel<<<(n4w + 255) / 256, 256>>>(Wo, pWh, pWl, n4w);
    gemm_bf16x3<<<gg, 256, GSMEM>>>(pAh, pAl, pWh, pWl, bo, nullptr, nullptr, out,
                                    MROWS, DMODEL, DMODEL, 2);
}

// round 13
// speedup vs baseline: 3.7565x; 1.4490x over previous
#include <cuda_runtime.h>
#include <cuda_bf16.h>
#include <math.h>
#include <stdint.h>

#define BATCH  4
#define SEQ    2048
#define DMODEL 2048
#define NHEAD  16
#define HDIM   128
#define MROWS  (BATCH * SEQ)   // 8192

typedef __nv_bfloat16 bf16;

// ---------------------------------------------------------------------------
// Scratch (device globals; no runtime allocation allowed)
// Q/K/V/attn stored in [B,S,D] (= [M,D]) layout, hi/lo bf16 pairs.
// ---------------------------------------------------------------------------
__device__ bf16 g_xh[(size_t)MROWS * DMODEL];
__device__ bf16 g_xl[(size_t)MROWS * DMODEL];
__device__ bf16 g_Wh[(size_t)DMODEL * DMODEL];
__device__ bf16 g_Wl[(size_t)DMODEL * DMODEL];
__device__ bf16 g_Qh[(size_t)MROWS * DMODEL];
__device__ bf16 g_Ql[(size_t)MROWS * DMODEL];
__device__ bf16 g_Kh[(size_t)MROWS * DMODEL];
__device__ bf16 g_Kl[(size_t)MROWS * DMODEL];
__device__ bf16 g_Vh[(size_t)MROWS * DMODEL];
__device__ bf16 g_Vl[(size_t)MROWS * DMODEL];
__device__ bf16 g_Ah[(size_t)MROWS * DMODEL];
__device__ bf16 g_Al[(size_t)MROWS * DMODEL];
__device__ uint32_t g_maskp[(size_t)BATCH * SEQ * (SEQ / 32)];   // 2MB packed mask

// ---------------------------------------------------------------------------
// Helpers
// ---------------------------------------------------------------------------
__device__ __forceinline__ void ldsm_x4(uint32_t r[4], const void* p) {
    uint32_t a = (uint32_t)__cvta_generic_to_shared(p);
    asm volatile("ldmatrix.sync.aligned.m8n8.x4.shared.b16 {%0,%1,%2,%3}, [%4];"
                 : "=r"(r[0]), "=r"(r[1]), "=r"(r[2]), "=r"(r[3]) : "r"(a));
}
__device__ __forceinline__ void ldsm_x4t(uint32_t r[4], const void* p) {
    uint32_t a = (uint32_t)__cvta_generic_to_shared(p);
    asm volatile("ldmatrix.sync.aligned.m8n8.x4.trans.shared.b16 {%0,%1,%2,%3}, [%4];"
                 : "=r"(r[0]), "=r"(r[1]), "=r"(r[2]), "=r"(r[3]) : "r"(a));
}
__device__ __forceinline__ void mma_bf16(float c[4], const uint32_t a[4], const uint32_t b[2]) {
    asm volatile(
        "mma.sync.aligned.m16n8k16.row.col.f32.bf16.bf16.f32 "
        "{%0,%1,%2,%3}, {%4,%5,%6,%7}, {%8,%9}, {%0,%1,%2,%3};"
        : "+f"(c[0]), "+f"(c[1]), "+f"(c[2]), "+f"(c[3])
        : "r"(a[0]), "r"(a[1]), "r"(a[2]), "r"(a[3]), "r"(b[0]), "r"(b[1]));
}
__device__ __forceinline__ void cp16(void* s, const void* g) {
    uint32_t sa = (uint32_t)__cvta_generic_to_shared(s);
    asm volatile("cp.async.cg.shared.global [%0], [%1], 16;" :: "r"(sa), "l"(g));
}
__device__ __forceinline__ void cp_commit() { asm volatile("cp.async.commit_group;"); }

__device__ __forceinline__ uint32_t pack_bf16x2(float lo, float hi) {
    __nv_bfloat162 h2;
    h2.x = __float2bfloat16(lo);
    h2.y = __float2bfloat16(hi);
    return *(uint32_t*)&h2;
}

// ---------------------------------------------------------------------------
// Split fp32 -> (bf16 hi, bf16 lo)
// ---------------------------------------------------------------------------
__global__ __launch_bounds__(256) void split_kernel(
    const float* __restrict__ in, bf16* __restrict__ hi, bf16* __restrict__ lo, int n4)
{
    int i = blockIdx.x * 256 + threadIdx.x;
    if (i >= n4) return;
    float4 f = ((const float4*)in)[i];
    bf16 h0 = __float2bfloat16(f.x); bf16 l0 = __float2bfloat16(f.x - __bfloat162float(h0));
    bf16 h1 = __float2bfloat16(f.y); bf16 l1 = __float2bfloat16(f.y - __bfloat162float(h1));
    bf16 h2 = __float2bfloat16(f.z); bf16 l2 = __float2bfloat16(f.z - __bfloat162float(h2));
    bf16 h3 = __float2bfloat16(f.w); bf16 l3 = __float2bfloat16(f.w - __bfloat162float(h3));
    __nv_bfloat162 a, b;
    a.x = h0; a.y = h1; b.x = h2; b.y = h3;
    ((__nv_bfloat162*)hi)[2 * i] = a; ((__nv_bfloat162*)hi)[2 * i + 1] = b;
    a.x = l0; a.y = l1; b.x = l2; b.y = l3;
    ((__nv_bfloat162*)lo)[2 * i] = a; ((__nv_bfloat162*)lo)[2 * i + 1] = b;
}

// ---------------------------------------------------------------------------
// Pack int32 mask into bitfield: bit j of word i  <=>  mask[i*32+j] != 0
// ---------------------------------------------------------------------------
__global__ __launch_bounds__(256) void pack_mask(
    const int* __restrict__ mask, uint32_t* __restrict__ out, int nw)
{
    int i = blockIdx.x * 256 + threadIdx.x;
    if (i >= nw) return;
    const int4* p = (const int4*)mask + (size_t)i * 8;
    uint32_t w = 0;
    #pragma unroll
    for (int j = 0; j < 8; j++) {
        int4 v = p[j];
        w |= (v.x != 0 ? 1u : 0u) << (j * 4 + 0);
        w |= (v.y != 0 ? 1u : 0u) << (j * 4 + 1);
        w |= (v.z != 0 ? 1u : 0u) << (j * 4 + 2);
        w |= (v.w != 0 ? 1u : 0u) << (j * 4 + 3);
    }
    out[i] = w;
}

// ---------------------------------------------------------------------------
// GEMM bf16x3 (mma.sync): C = Ah*Bh + Ah*Bl + Al*Bh + bias (fp32 accum)
// A [M,K] row-major hi/lo, B [K,N] row-major hi/lo.
// mode 0: write Ch/Cl [M,N] bf16 hi/lo;  mode 2: write Cf fp32 [M,N].
// Tiles 128x128x32, 256 threads (8 warps, 32m x 64n each), cp.async dbuf.
// ---------------------------------------------------------------------------
#define GBK 32
#define AP  40
#define BP  136
#define A_ST (128 * AP * 2)
#define B_ST (GBK * BP * 2)
#define GSM_AH 0
#define GSM_AL (2 * A_ST)
#define GSM_BH (4 * A_ST)
#define GSM_BL (4 * A_ST + 2 * B_ST)
#define GSMEM  (4 * A_ST + 4 * B_ST)   // 75776 B

__global__ __launch_bounds__(256, 2) void gemm_bf16x3(
    const bf16* __restrict__ Agh, const bf16* __restrict__ Agl,
    const bf16* __restrict__ Bgh, const bf16* __restrict__ Bgl,
    const float* __restrict__ bias,
    bf16* __restrict__ Ch, bf16* __restrict__ Cl, float* __restrict__ Cf,
    int M, int N, int K, int mode)
{
    extern __shared__ char sm[];
    const int tid = threadIdx.x;
    const int l   = tid & 31;
    const int wid = tid >> 5;
    const int wm  = (wid & 3) * 32;
    const int wn  = (wid >> 2) * 64;
    const int m0  = blockIdx.y * 128;
    const int n0  = blockIdx.x * 128;

    float acc[2][8][4];
    #pragma unroll
    for (int mt = 0; mt < 2; mt++)
        #pragma unroll
        for (int nt = 0; nt < 8; nt++)
            #pragma unroll
            for (int q = 0; q < 4; q++) acc[mt][nt][q] = 0.f;

    auto issue = [&](int k0, int st) {
        char* pAh = sm + GSM_AH + st * A_ST;
        char* pAl = sm + GSM_AL + st * A_ST;
        char* pBh = sm + GSM_BH + st * B_ST;
        char* pBl = sm + GSM_BL + st * B_ST;
        #pragma unroll
        for (int j = 0; j < 2; j++) {
            int u  = tid + j * 256;
            int r  = u >> 2;
            int c8 = (u & 3) * 8;
            size_t ga = (size_t)(m0 + r) * K + k0 + c8;
            cp16(pAh + (r * AP + c8) * 2, Agh + ga);
            cp16(pAl + (r * AP + c8) * 2, Agl + ga);
            int rb  = u >> 4;
            int cb8 = (u & 15) * 8;
            size_t gb = (size_t)(k0 + rb) * N + n0 + cb8;
            cp16(pBh + (rb * BP + cb8) * 2, Bgh + gb);
            cp16(pBl + (rb * BP + cb8) * 2, Bgl + gb);
        }
    };

    issue(0, 0); cp_commit();
    asm volatile("cp.async.wait_group 0;");
    __syncthreads();

    int st = 0;
    for (int k0 = 0; k0 < K; k0 += GBK) {
        const bool nxt = (k0 + GBK) < K;
        if (nxt) { issue(k0 + GBK, st ^ 1); cp_commit(); }

        char* pAh = sm + GSM_AH + st * A_ST;
        char* pAl = sm + GSM_AL + st * A_ST;
        char* pBh = sm + GSM_BH + st * B_ST;
        char* pBl = sm + GSM_BL + st * B_ST;

        #pragma unroll
        for (int ks = 0; ks < 2; ks++) {
            uint32_t ah[2][4], al[2][4];
            #pragma unroll
            for (int mt = 0; mt < 2; mt++) {
                int off = ((wm + mt * 16 + (l & 15)) * AP + ks * 16 + ((l & 16) >> 1)) * 2;
                ldsm_x4(ah[mt], pAh + off);
                ldsm_x4(al[mt], pAl + off);
            }
            uint32_t bh[4][4], bl[4][4];
            #pragma unroll
            for (int q = 0; q < 4; q++) {
                int off = ((ks * 16 + (l & 15)) * BP + wn + q * 16 + ((l & 16) >> 1)) * 2;
                ldsm_x4t(bh[q], pBh + off);
                ldsm_x4t(bl[q], pBl + off);
            }
            #pragma unroll
            for (int mt = 0; mt < 2; mt++)
                #pragma unroll
                for (int nt = 0; nt < 8; nt++) {
                    const uint32_t* bhp = &bh[nt >> 1][(nt & 1) * 2];
                    const uint32_t* blp = &bl[nt >> 1][(nt & 1) * 2];
                    mma_bf16(acc[mt][nt], ah[mt], bhp);
                    mma_bf16(acc[mt][nt], ah[mt], blp);
                    mma_bf16(acc[mt][nt], al[mt], bhp);
                }
        }
        if (nxt) asm volatile("cp.async.wait_group 0;");
        __syncthreads();
        st ^= 1;
    }

    #pragma unroll
    for (int mt = 0; mt < 2; mt++) {
        #pragma unroll
        for (int nt = 0; nt < 8; nt++) {
            int r0 = m0 + wm + mt * 16 + (l >> 2);
            int c  = n0 + wn + nt * 8 + (l & 3) * 2;
            float v[4];
            v[0] = acc[mt][nt][0] + bias[c];
            v[1] = acc[mt][nt][1] + bias[c + 1];
            v[2] = acc[mt][nt][2] + bias[c];
            v[3] = acc[mt][nt][3] + bias[c + 1];
            #pragma unroll
            for (int e = 0; e < 4; e++) {
                int row = r0 + (e >> 1) * 8;
                int col = c + (e & 1);
                size_t idx = (size_t)row * N + col;
                if (mode == 2) {
                    Cf[idx] = v[e];
                } else {
                    bf16 hh = __float2bfloat16(v[e]);
                    Ch[idx] = hh;
                    Cl[idx] = __float2bfloat16(v[e] - __bfloat162float(hh));
                }
            }
        }
    }
}

// ---------------------------------------------------------------------------
// Flash attention, register-resident FA2 (mma.sync bf16x3).
// Br=128, Bc=64, hd=128, 256 threads (8 warps; warp = 16 rows x full width).
// S kept in mma accumulators; softmax via shfl; P fragments built from S
// accumulators directly (c-frag -> a-frag identity). K/V cp.async dbuf.
// ---------------------------------------------------------------------------
#define FBR 128
#define FBC 64
#define FP  136                       // padded pitch (halves)
#define FQ_SZ (FBR * FP * 2)          // 34816
#define FKV_SZ (FBC * FP * 2)         // 17408
#define F_QH 0
#define F_QL (F_QH + FQ_SZ)
#define F_ST0 (F_QL + FQ_SZ)          // 69632
#define F_STG (4 * FKV_SZ)            // 69632 per stage
#define F_KH(st) (F_ST0 + (st) * F_STG)
#define F_KL(st) (F_KH(st) + FKV_SZ)
#define F_VH(st) (F_KL(st) + FKV_SZ)
#define F_VL(st) (F_VH(st) + FKV_SZ)
#define FSMEM (F_ST0 + 2 * F_STG)     // 208896

__global__ __launch_bounds__(256) void flash_bf16(
    const bf16* __restrict__ Qh, const bf16* __restrict__ Ql,
    const bf16* __restrict__ Kh, const bf16* __restrict__ Kl,
    const bf16* __restrict__ Vh, const bf16* __restrict__ Vl,
    const uint32_t* __restrict__ maskp,
    bf16* __restrict__ Oh, bf16* __restrict__ Ol)
{
    extern __shared__ char sm[];
    const int tid = threadIdx.x;
    const int l   = tid & 31;
    const int wid = tid >> 5;
    const int g   = l >> 2;            // row group within warp tile
    const int t   = l & 3;             // col quad
    const int wm  = wid * 16;          // warp's first row in tile
    const int bh  = blockIdx.y;
    const int q0  = blockIdx.x * FBR;
    const int b   = bh >> 4;
    const int h   = bh & 15;
    const float NEG_INF = __int_as_float(0xff800000);
    const float SCALE = 0.08838834764831845f;

    // load Q tile (128 x 128 hi/lo) into smem
    {
        const size_t qb = ((size_t)(b * SEQ + q0)) * DMODEL + (size_t)h * HDIM;
        #pragma unroll
        for (int j = 0; j < 8; j++) {
            int u = tid + j * 256;                 // 0..2047
            int r = u >> 4, c8 = (u & 15) * 8;
            size_t gp = qb + (size_t)r * DMODEL + c8;
            *(uint4*)(sm + F_QH + (r * FP + c8) * 2) = *(const uint4*)(Qh + gp);
            *(uint4*)(sm + F_QL + (r * FP + c8) * 2) = *(const uint4*)(Ql + gp);
        }
    }

    auto issue_kv = [&](int kt, int st) {
        const size_t kb = ((size_t)(b * SEQ + kt * FBC)) * DMODEL + (size_t)h * HDIM;
        char* KH = sm + F_KH(st); char* KL = sm + F_KL(st);
        char* VH = sm + F_VH(st); char* VL = sm + F_VL(st);
        #pragma unroll
        for (int j = 0; j < 4; j++) {
            int u = tid + j * 256;                 // 0..1023
            int r = u >> 4, c8 = (u & 15) * 8;
            size_t gp = kb + (size_t)r * DMODEL + c8;
            int so = (r * FP + c8) * 2;
            cp16(KH + so, Kh + gp);
            cp16(KL + so, Kl + gp);
            cp16(VH + so, Vh + gp);
            cp16(VL + so, Vl + gp);
        }
    };

    issue_kv(0, 0); cp_commit();
    issue_kv(1, 1); cp_commit();

    // per-thread softmax state (rows r0 = q0+wm+g, r1 = r0+8)
    float m0r = NEG_INF, m1r = NEG_INF, l0r = 0.f, l1r = 0.f;
    float oacc[16][4];
    #pragma unroll
    for (int nt = 0; nt < 16; nt++)
        #pragma unroll
        for (int q = 0; q < 4; q++) oacc[nt][q] = 0.f;

    const int NT = SEQ / FBC;   // 32
    const size_t mrow0 = ((size_t)b * SEQ + q0 + wm + g) * (SEQ / 32);
    const size_t mrow1 = mrow0 + 8 * (SEQ / 32);

    for (int kt = 0; kt < NT; kt++) {
        asm volatile("cp.async.wait_group 1;");
        __syncthreads();
        const int st = kt & 1;
        const char* KH = sm + F_KH(st); const char* KL = sm + F_KL(st);
        const char* VH = sm + F_VH(st); const char* VL = sm + F_VL(st);

        // ---- S = Q K^T (bf16x3), warp tile 16m x 64n ----
        float sacc[8][4];
        #pragma unroll
        for (int nt = 0; nt < 8; nt++)
            #pragma unroll
            for (int q = 0; q < 4; q++) sacc[nt][q] = 0.f;

        #pragma unroll
        for (int ks = 0; ks < 8; ks++) {
            uint32_t qh4[4], ql4[4];
            int qoff = ((wm + (l & 15)) * FP + ks * 16 + ((l & 16) >> 1)) * 2;
            ldsm_x4(qh4, sm + F_QH + qoff);
            ldsm_x4(ql4, sm + F_QL + qoff);
            #pragma unroll
            for (int q = 0; q < 4; q++) {
                uint32_t kh4[4], kl4[4];
                int nr = q * 16 + (l & 7) + ((l & 16) >> 1);
                int kc = ks * 16 + (l & 8);
                int off = (nr * FP + kc) * 2;
                ldsm_x4(kh4, KH + off);
                ldsm_x4(kl4, KL + off);
                #pragma unroll
                for (int half = 0; half < 2; half++) {
                    const uint32_t* bhp = &kh4[half * 2];
                    const uint32_t* blp = &kl4[half * 2];
                    float* s = sacc[q * 2 + half];
                    mma_bf16(s, qh4, bhp);
                    mma_bf16(s, qh4, blp);
                    mma_bf16(s, ql4, bhp);
                }
            }
        }

        // ---- scale + mask (packed bits) + row max ----
        const uint32_t w00 = maskp[mrow0 + kt * 2];
        const uint32_t w01 = maskp[mrow0 + kt * 2 + 1];
        const uint32_t w10 = maskp[mrow1 + kt * 2];
        const uint32_t w11 = maskp[mrow1 + kt * 2 + 1];

        float mx0 = NEG_INF, mx1 = NEG_INF;
        #pragma unroll
        for (int nt = 0; nt < 8; nt++) {
            const int c  = nt * 8 + 2 * t;
            const int sh = c & 31;
            const uint32_t wr0 = (nt < 4) ? w00 : w01;
            const uint32_t wr1 = (nt < 4) ? w10 : w11;
            float v0 = sacc[nt][0] * SCALE; if (!((wr0 >> sh) & 1))       v0 = NEG_INF;
            float v1 = sacc[nt][1] * SCALE; if (!((wr0 >> (sh + 1)) & 1)) v1 = NEG_INF;
            float v2 = sacc[nt][2] * SCALE; if (!((wr1 >> sh) & 1))       v2 = NEG_INF;
            float v3 = sacc[nt][3] * SCALE; if (!((wr1 >> (sh + 1)) & 1)) v3 = NEG_INF;
            sacc[nt][0] = v0; sacc[nt][1] = v1; sacc[nt][2] = v2; sacc[nt][3] = v3;
            mx0 = fmaxf(mx0, fmaxf(v0, v1));
            mx1 = fmaxf(mx1, fmaxf(v2, v3));
        }
        mx0 = fmaxf(mx0, __shfl_xor_sync(0xffffffffu, mx0, 1));
        mx0 = fmaxf(mx0, __shfl_xor_sync(0xffffffffu, mx0, 2));
        mx1 = fmaxf(mx1, __shfl_xor_sync(0xffffffffu, mx1, 1));
        mx1 = fmaxf(mx1, __shfl_xor_sync(0xffffffffu, mx1, 2));

        const float mn0 = fmaxf(m0r, mx0);
        const float mn1 = fmaxf(m1r, mx1);
        const float al0 = (m0r == NEG_INF) ? 0.f : __expf(m0r - mn0);
        const float al1 = (m1r == NEG_INF) ? 0.f : __expf(m1r - mn1);
        m0r = mn0; m1r = mn1;

        // ---- P = exp(S - m), rowsum, in-register ----
        float sum0 = 0.f, sum1 = 0.f;
        #pragma unroll
        for (int nt = 0; nt < 8; nt++) {
            float p0 = __expf(sacc[nt][0] - mn0);
            float p1 = __expf(sacc[nt][1] - mn0);
            float p2 = __expf(sacc[nt][2] - mn1);
            float p3 = __expf(sacc[nt][3] - mn1);
            sacc[nt][0] = p0; sacc[nt][1] = p1; sacc[nt][2] = p2; sacc[nt][3] = p3;
            sum0 += p0 + p1;
            sum1 += p2 + p3;
        }
        sum0 += __shfl_xor_sync(0xffffffffu, sum0, 1);
        sum0 += __shfl_xor_sync(0xffffffffu, sum0, 2);
        sum1 += __shfl_xor_sync(0xffffffffu, sum1, 1);
        sum1 += __shfl_xor_sync(0xffffffffu, sum1, 2);
        l0r = l0r * al0 + sum0;
        l1r = l1r * al1 + sum1;

        // ---- rescale O ----
        #pragma unroll
        for (int nt = 0; nt < 16; nt++) {
            oacc[nt][0] *= al0; oacc[nt][1] *= al0;
            oacc[nt][2] *= al1; oacc[nt][3] *= al1;
        }

        // ---- O += P V (bf16x3); P a-frags built from sacc directly ----
        #pragma unroll
        for (int s = 0; s < 4; s++) {
            // a-frag: a0=(g,lowk) a1=(g+8,lowk) a2=(g,highk) a3=(g+8,highk)
            uint32_t pah[4], pal[4];
            {
                const float* c0 = sacc[2 * s];
                const float* c1 = sacc[2 * s + 1];
                pah[0] = pack_bf16x2(c0[0], c0[1]);
                pah[1] = pack_bf16x2(c0[2], c0[3]);
                pah[2] = pack_bf16x2(c1[0], c1[1]);
                pah[3] = pack_bf16x2(c1[2], c1[3]);
                __nv_bfloat162 h2;
                h2 = *(__nv_bfloat162*)&pah[0];
                pal[0] = pack_bf16x2(c0[0] - __bfloat162float(h2.x), c0[1] - __bfloat162float(h2.y));
                h2 = *(__nv_bfloat162*)&pah[1];
                pal[1] = pack_bf16x2(c0[2] - __bfloat162float(h2.x), c0[3] - __bfloat162float(h2.y));
                h2 = *(__nv_bfloat162*)&pah[2];
                pal[2] = pack_bf16x2(c1[0] - __bfloat162float(h2.x), c1[1] - __bfloat162float(h2.y));
                h2 = *(__nv_bfloat162*)&pah[3];
                pal[3] = pack_bf16x2(c1[2] - __bfloat162float(h2.x), c1[3] - __bfloat162float(h2.y));
            }
            #pragma unroll
            for (int q = 0; q < 8; q++) {
                uint32_t vh4[4], vl4[4];
                int vr = s * 16 + (l & 15);
                int vc = q * 16 + ((l & 16) >> 1);
                int off = (vr * FP + vc) * 2;
                ldsm_x4t(vh4, VH + off);
                ldsm_x4t(vl4, VL + off);
                #pragma unroll
                for (int half = 0; half < 2; half++) {
                    const uint32_t* bhp = &vh4[half * 2];
                    const uint32_t* blp = &vl4[half * 2];
                    float* o = oacc[q * 2 + half];
                    mma_bf16(o, pah, bhp);
                    mma_bf16(o, pah, blp);
                    mma_bf16(o, pal, bhp);
                }
            }
        }

        __syncthreads();                    // stage fully consumed
        if (kt + 2 < NT) issue_kv(kt + 2, st);
        cp_commit();                        // keep group count uniform
    }

    // ---- epilogue: normalize, write hi/lo to [B,S,D] ----
    {
        const float inv0 = 1.f / l0r;
        const float inv1 = 1.f / l1r;
        const int r0 = q0 + wm + g;
        const int r1 = r0 + 8;
        const size_t b0 = ((size_t)(b * SEQ + r0)) * DMODEL + (size_t)h * HDIM;
        const size_t b1 = ((size_t)(b * SEQ + r1)) * DMODEL + (size_t)h * HDIM;
        #pragma unroll
        for (int nt = 0; nt < 16; nt++) {
            const int c = nt * 8 + 2 * t;
            float v00 = oacc[nt][0] * inv0, v01 = oacc[nt][1] * inv0;
            float v10 = oacc[nt][2] * inv1, v11 = oacc[nt][3] * inv1;
            uint32_t h0 = pack_bf16x2(v00, v01);
            uint32_t h1 = pack_bf16x2(v10, v11);
            __nv_bfloat162 hh;
            hh = *(__nv_bfloat162*)&h0;
            uint32_t l0 = pack_bf16x2(v00 - __bfloat162float(hh.x), v01 - __bfloat162float(hh.y));
            hh = *(__nv_bfloat162*)&h1;
            uint32_t l1 = pack_bf16x2(v10 - __bfloat162float(hh.x), v11 - __bfloat162float(hh.y));
            *(uint32_t*)(Oh + b0 + c) = h0;
            *(uint32_t*)(Ol + b0 + c) = l0;
            *(uint32_t*)(Oh + b1 + c) = h1;
            *(uint32_t*)(Ol + b1 + c) = l1;
        }
    }
}

// ---------------------------------------------------------------------------
// Launch
// ---------------------------------------------------------------------------
extern "C" void kernel_launch(void* const* d_in, const int* in_sizes, int n_in,
                              void* d_out, int out_size)
{
    const float* x    = (const float*)d_in[0];
    const int*   mask = (const int*)  d_in[1];
    const float* Wq   = (const float*)d_in[2];
    const float* bq   = (const float*)d_in[3];
    const float* Wk   = (const float*)d_in[4];
    const float* bk   = (const float*)d_in[5];
    const float* Wv   = (const float*)d_in[6];
    const float* bv   = (const float*)d_in[7];
    const float* Wo   = (const float*)d_in[8];
    const float* bo   = (const float*)d_in[9];
    float* out = (float*)d_out;

    bf16 *pxh, *pxl, *pWh, *pWl, *pQh, *pQl, *pKh, *pKl, *pVh, *pVl, *pAh, *pAl;
    uint32_t* pMp;
    cudaGetSymbolAddress((void**)&pxh, g_xh);
    cudaGetSymbolAddress((void**)&pxl, g_xl);
    cudaGetSymbolAddress((void**)&pWh, g_Wh);
    cudaGetSymbolAddress((void**)&pWl, g_Wl);
    cudaGetSymbolAddress((void**)&pQh, g_Qh);
    cudaGetSymbolAddress((void**)&pQl, g_Ql);
    cudaGetSymbolAddress((void**)&pKh, g_Kh);
    cudaGetSymbolAddress((void**)&pKl, g_Kl);
    cudaGetSymbolAddress((void**)&pVh, g_Vh);
    cudaGetSymbolAddress((void**)&pVl, g_Vl);
    cudaGetSymbolAddress((void**)&pAh, g_Ah);
    cudaGetSymbolAddress((void**)&pAl, g_Al);
    cudaGetSymbolAddress((void**)&pMp, g_maskp);

    cudaFuncSetAttribute(gemm_bf16x3, cudaFuncAttributeMaxDynamicSharedMemorySize, GSMEM);
    cudaFuncSetAttribute(flash_bf16, cudaFuncAttributeMaxDynamicSharedMemorySize, FSMEM);

    const int n4x = MROWS * DMODEL / 4;
    const int n4w = DMODEL * DMODEL / 4;
    const int nw  = BATCH * SEQ * (SEQ / 32);
    const dim3 gg(DMODEL / 128, MROWS / 128);   // (16, 64)

    split_kernel<<<(n4x + 255) / 256, 256>>>(x, pxh, pxl, n4x);
    pack_mask<<<(nw + 255) / 256, 256>>>(mask, pMp, nw);

    split_kernel<<<(n4w + 255) / 256, 256>>>(Wq, pWh, pWl, n4w);
    gemm_bf16x3<<<gg, 256, GSMEM>>>(pxh, pxl, pWh, pWl, bq, pQh, pQl, nullptr,
                                    MROWS, DMODEL, DMODEL, 0);
    split_kernel<<<(n4w + 255) / 256, 256>>>(Wk, pWh, pWl, n4w);
    gemm_bf16x3<<<gg, 256, GSMEM>>>(pxh, pxl, pWh, pWl, bk, pKh, pKl, nullptr,
                                    MROWS, DMODEL, DMODEL, 0);
    split_kernel<<<(n4w + 255) / 256, 256>>>(Wv, pWh, pWl, n4w);
    gemm_bf16x3<<<gg, 256, GSMEM>>>(pxh, pxl, pWh, pWl, bv, pVh, pVl, nullptr,
                                    MROWS, DMODEL, DMODEL, 0);

    flash_bf16<<<dim3(SEQ / FBR, BATCH * NHEAD), 256, FSMEM>>>(
        pQh, pQl, pKh, pKl, pVh, pVl, pMp, pAh, pAl);

    split_kernel<<<(n4w + 255) / 256, 256>>>(Wo, pWh, pWl, n4w);
    gemm_bf16x3<<<gg, 256, GSMEM>>>(pAh, pAl, pWh, pWl, bo, nullptr, nullptr, out,
                                    MROWS, DMODEL, DMODEL, 2);
}

// round 14
// speedup vs baseline: 4.1731x; 1.1109x over previous
#include <cuda_runtime.h>
#include <cuda_bf16.h>
#include <cuda_fp16.h>
#include <math.h>
#include <stdint.h>

#define BATCH  4
#define SEQ    2048
#define DMODEL 2048
#define NHEAD  16
#define HDIM   128
#define MROWS  (BATCH * SEQ)   // 8192
#define WSZ    ((size_t)DMODEL * DMODEL)

typedef __nv_bfloat16 bf16;

// ---------------------------------------------------------------------------
// Scratch (device globals; no runtime allocation allowed)
// ---------------------------------------------------------------------------
__device__ bf16 g_xh[(size_t)MROWS * DMODEL];
__device__ bf16 g_xl[(size_t)MROWS * DMODEL];
__device__ bf16 g_Wh[4 * WSZ];    // 4 weight slots: q,k,v,o (transposed? no - [K,N] row-major)
__device__ bf16 g_Wl[4 * WSZ];
__device__ bf16 g_Qh[(size_t)MROWS * DMODEL];
__device__ bf16 g_Ql[(size_t)MROWS * DMODEL];
__device__ bf16 g_Kh[(size_t)MROWS * DMODEL];
__device__ bf16 g_Kl[(size_t)MROWS * DMODEL];
__device__ __half g_Vf[(size_t)MROWS * DMODEL];     // V single fp16
__device__ bf16 g_Ah[(size_t)MROWS * DMODEL];
__device__ bf16 g_Al[(size_t)MROWS * DMODEL];
__device__ uint32_t g_maskp[(size_t)BATCH * SEQ * (SEQ / 32)];

// ---------------------------------------------------------------------------
// Helpers
// ---------------------------------------------------------------------------
__device__ __forceinline__ void ldsm_x4(uint32_t r[4], const void* p) {
    uint32_t a = (uint32_t)__cvta_generic_to_shared(p);
    asm volatile("ldmatrix.sync.aligned.m8n8.x4.shared.b16 {%0,%1,%2,%3}, [%4];"
                 : "=r"(r[0]), "=r"(r[1]), "=r"(r[2]), "=r"(r[3]) : "r"(a));
}
__device__ __forceinline__ void ldsm_x4t(uint32_t r[4], const void* p) {
    uint32_t a = (uint32_t)__cvta_generic_to_shared(p);
    asm volatile("ldmatrix.sync.aligned.m8n8.x4.trans.shared.b16 {%0,%1,%2,%3}, [%4];"
                 : "=r"(r[0]), "=r"(r[1]), "=r"(r[2]), "=r"(r[3]) : "r"(a));
}
__device__ __forceinline__ void mma_bf16(float c[4], const uint32_t a[4], const uint32_t b[2]) {
    asm volatile(
        "mma.sync.aligned.m16n8k16.row.col.f32.bf16.bf16.f32 "
        "{%0,%1,%2,%3}, {%4,%5,%6,%7}, {%8,%9}, {%0,%1,%2,%3};"
        : "+f"(c[0]), "+f"(c[1]), "+f"(c[2]), "+f"(c[3])
        : "r"(a[0]), "r"(a[1]), "r"(a[2]), "r"(a[3]), "r"(b[0]), "r"(b[1]));
}
__device__ __forceinline__ void mma_f16(float c[4], const uint32_t a[4], const uint32_t b[2]) {
    asm volatile(
        "mma.sync.aligned.m16n8k16.row.col.f32.f16.f16.f32 "
        "{%0,%1,%2,%3}, {%4,%5,%6,%7}, {%8,%9}, {%0,%1,%2,%3};"
        : "+f"(c[0]), "+f"(c[1]), "+f"(c[2]), "+f"(c[3])
        : "r"(a[0]), "r"(a[1]), "r"(a[2]), "r"(a[3]), "r"(b[0]), "r"(b[1]));
}
__device__ __forceinline__ void cp16(void* s, const void* g) {
    uint32_t sa = (uint32_t)__cvta_generic_to_shared(s);
    asm volatile("cp.async.cg.shared.global [%0], [%1], 16;" :: "r"(sa), "l"(g));
}
__device__ __forceinline__ void cp_commit() { asm volatile("cp.async.commit_group;"); }

__device__ __forceinline__ uint32_t pack_bf16x2(float lo, float hi) {
    __nv_bfloat162 h2;
    h2.x = __float2bfloat16(lo);
    h2.y = __float2bfloat16(hi);
    return *(uint32_t*)&h2;
}
__device__ __forceinline__ uint32_t pack_f16x2(float lo, float hi) {
    __half2 h2 = __floats2half2_rn(lo, hi);
    return *(uint32_t*)&h2;
}

// ---------------------------------------------------------------------------
// Split fp32 -> (bf16 hi, bf16 lo)  (activations x)
// ---------------------------------------------------------------------------
__global__ __launch_bounds__(256) void split_kernel(
    const float* __restrict__ in, bf16* __restrict__ hi, bf16* __restrict__ lo, int n4)
{
    int i = blockIdx.x * 256 + threadIdx.x;
    if (i >= n4) return;
    float4 f = ((const float4*)in)[i];
    bf16 h0 = __float2bfloat16(f.x); bf16 l0 = __float2bfloat16(f.x - __bfloat162float(h0));
    bf16 h1 = __float2bfloat16(f.y); bf16 l1 = __float2bfloat16(f.y - __bfloat162float(h1));
    bf16 h2 = __float2bfloat16(f.z); bf16 l2 = __float2bfloat16(f.z - __bfloat162float(h2));
    bf16 h3 = __float2bfloat16(f.w); bf16 l3 = __float2bfloat16(f.w - __bfloat162float(h3));
    __nv_bfloat162 a, b;
    a.x = h0; a.y = h1; b.x = h2; b.y = h3;
    ((__nv_bfloat162*)hi)[2 * i] = a; ((__nv_bfloat162*)hi)[2 * i + 1] = b;
    a.x = l0; a.y = l1; b.x = l2; b.y = l3;
    ((__nv_bfloat162*)lo)[2 * i] = a; ((__nv_bfloat162*)lo)[2 * i + 1] = b;
}

// ---------------------------------------------------------------------------
// Split all 4 weights into the 4-slot hi/lo buffers. grid (n4w/256, 4)
// ---------------------------------------------------------------------------
__global__ __launch_bounds__(256) void split_w4(
    const float* __restrict__ w0, const float* __restrict__ w1,
    const float* __restrict__ w2, const float* __restrict__ w3,
    bf16* __restrict__ hi, bf16* __restrict__ lo)
{
    const int widx = blockIdx.y;
    const float* src = (widx == 0) ? w0 : (widx == 1) ? w1 : (widx == 2) ? w2 : w3;
    bf16* hp = hi + (size_t)widx * WSZ;
    bf16* lp = lo + (size_t)widx * WSZ;
    int i = blockIdx.x * 256 + threadIdx.x;   // < WSZ/4
    float4 f = ((const float4*)src)[i];
    bf16 h0 = __float2bfloat16(f.x); bf16 l0 = __float2bfloat16(f.x - __bfloat162float(h0));
    bf16 h1 = __float2bfloat16(f.y); bf16 l1 = __float2bfloat16(f.y - __bfloat162float(h1));
    bf16 h2 = __float2bfloat16(f.z); bf16 l2 = __float2bfloat16(f.z - __bfloat162float(h2));
    bf16 h3 = __float2bfloat16(f.w); bf16 l3 = __float2bfloat16(f.w - __bfloat162float(h3));
    __nv_bfloat162 a, b;
    a.x = h0; a.y = h1; b.x = h2; b.y = h3;
    ((__nv_bfloat162*)hp)[2 * i] = a; ((__nv_bfloat162*)hp)[2 * i + 1] = b;
    a.x = l0; a.y = l1; b.x = l2; b.y = l3;
    ((__nv_bfloat162*)lp)[2 * i] = a; ((__nv_bfloat162*)lp)[2 * i + 1] = b;
}

// ---------------------------------------------------------------------------
// Pack int32 mask into bitfield
// ---------------------------------------------------------------------------
__global__ __launch_bounds__(256) void pack_mask(
    const int* __restrict__ mask, uint32_t* __restrict__ out, int nw)
{
    int i = blockIdx.x * 256 + threadIdx.x;
    if (i >= nw) return;
    const int4* p = (const int4*)mask + (size_t)i * 8;
    uint32_t w = 0;
    #pragma unroll
    for (int j = 0; j < 8; j++) {
        int4 v = p[j];
        w |= (v.x != 0 ? 1u : 0u) << (j * 4 + 0);
        w |= (v.y != 0 ? 1u : 0u) << (j * 4 + 1);
        w |= (v.z != 0 ? 1u : 0u) << (j * 4 + 2);
        w |= (v.w != 0 ? 1u : 0u) << (j * 4 + 3);
    }
    out[i] = w;
}

// ---------------------------------------------------------------------------
// GEMM bf16x3 (mma.sync). One kernel serves:
//   QKV fused: grid.z = 3, weight slot = z; z 0/1 -> bf16 hi/lo (Q,K);
//              z 2 -> fp16 single (V). Cf == nullptr.
//   O:         grid.z = 1, wslot0 = 3, Cf = fp32 out.
// Tiles 128x128x32, 256 threads (8 warps, 32m x 64n), cp.async dbuf.
// ---------------------------------------------------------------------------
#define GBK 32
#define AP  40
#define BP  136
#define A_ST (128 * AP * 2)
#define B_ST (GBK * BP * 2)
#define GSM_AH 0
#define GSM_AL (2 * A_ST)
#define GSM_BH (4 * A_ST)
#define GSM_BL (4 * A_ST + 2 * B_ST)
#define GSMEM  (4 * A_ST + 4 * B_ST)   // 75776 B

__global__ __launch_bounds__(256, 2) void gemm_bf16x3(
    const bf16* __restrict__ Agh, const bf16* __restrict__ Agl,
    const bf16* __restrict__ Wh4, const bf16* __restrict__ Wl4,
    const float* __restrict__ b0, const float* __restrict__ b1, const float* __restrict__ b2,
    bf16* __restrict__ C0h, bf16* __restrict__ C0l,
    bf16* __restrict__ C1h, bf16* __restrict__ C1l,
    __half* __restrict__ C2f,
    float* __restrict__ Cf, int wslot0)
{
    extern __shared__ char sm[];
    const int z   = blockIdx.z;
    const bf16* Bgh = Wh4 + (size_t)(wslot0 + z) * WSZ;
    const bf16* Bgl = Wl4 + (size_t)(wslot0 + z) * WSZ;
    const float* bias = (z == 0) ? b0 : (z == 1) ? b1 : b2;

    const int tid = threadIdx.x;
    const int l   = tid & 31;
    const int wid = tid >> 5;
    const int wm  = (wid & 3) * 32;
    const int wn  = (wid >> 2) * 64;
    const int m0  = blockIdx.y * 128;
    const int n0  = blockIdx.x * 128;
    const int K = DMODEL, N = DMODEL;

    float acc[2][8][4];
    #pragma unroll
    for (int mt = 0; mt < 2; mt++)
        #pragma unroll
        for (int nt = 0; nt < 8; nt++)
            #pragma unroll
            for (int q = 0; q < 4; q++) acc[mt][nt][q] = 0.f;

    auto issue = [&](int k0, int st) {
        char* pAh = sm + GSM_AH + st * A_ST;
        char* pAl = sm + GSM_AL + st * A_ST;
        char* pBh = sm + GSM_BH + st * B_ST;
        char* pBl = sm + GSM_BL + st * B_ST;
        #pragma unroll
        for (int j = 0; j < 2; j++) {
            int u  = tid + j * 256;
            int r  = u >> 2;
            int c8 = (u & 3) * 8;
            size_t ga = (size_t)(m0 + r) * K + k0 + c8;
            cp16(pAh + (r * AP + c8) * 2, Agh + ga);
            cp16(pAl + (r * AP + c8) * 2, Agl + ga);
            int rb  = u >> 4;
            int cb8 = (u & 15) * 8;
            size_t gb = (size_t)(k0 + rb) * N + n0 + cb8;
            cp16(pBh + (rb * BP + cb8) * 2, Bgh + gb);
            cp16(pBl + (rb * BP + cb8) * 2, Bgl + gb);
        }
    };

    issue(0, 0); cp_commit();
    asm volatile("cp.async.wait_group 0;");
    __syncthreads();

    int st = 0;
    for (int k0 = 0; k0 < K; k0 += GBK) {
        const bool nxt = (k0 + GBK) < K;
        if (nxt) { issue(k0 + GBK, st ^ 1); cp_commit(); }

        char* pAh = sm + GSM_AH + st * A_ST;
        char* pAl = sm + GSM_AL + st * A_ST;
        char* pBh = sm + GSM_BH + st * B_ST;
        char* pBl = sm + GSM_BL + st * B_ST;

        #pragma unroll
        for (int ks = 0; ks < 2; ks++) {
            uint32_t ah[2][4], al[2][4];
            #pragma unroll
            for (int mt = 0; mt < 2; mt++) {
                int off = ((wm + mt * 16 + (l & 15)) * AP + ks * 16 + ((l & 16) >> 1)) * 2;
                ldsm_x4(ah[mt], pAh + off);
                ldsm_x4(al[mt], pAl + off);
            }
            uint32_t bh[4][4], bl[4][4];
            #pragma unroll
            for (int q = 0; q < 4; q++) {
                int off = ((ks * 16 + (l & 15)) * BP + wn + q * 16 + ((l & 16) >> 1)) * 2;
                ldsm_x4t(bh[q], pBh + off);
                ldsm_x4t(bl[q], pBl + off);
            }
            #pragma unroll
            for (int mt = 0; mt < 2; mt++)
                #pragma unroll
                for (int nt = 0; nt < 8; nt++) {
                    const uint32_t* bhp = &bh[nt >> 1][(nt & 1) * 2];
                    const uint32_t* blp = &bl[nt >> 1][(nt & 1) * 2];
                    mma_bf16(acc[mt][nt], ah[mt], bhp);
                    mma_bf16(acc[mt][nt], ah[mt], blp);
                    mma_bf16(acc[mt][nt], al[mt], bhp);
                }
        }
        if (nxt) asm volatile("cp.async.wait_group 0;");
        __syncthreads();
        st ^= 1;
    }

    bf16* Ch = (z == 1) ? C1h : C0h;
    bf16* Cl = (z == 1) ? C1l : C0l;

    #pragma unroll
    for (int mt = 0; mt < 2; mt++) {
        #pragma unroll
        for (int nt = 0; nt < 8; nt++) {
            int r0 = m0 + wm + mt * 16 + (l >> 2);
            int c  = n0 + wn + nt * 8 + (l & 3) * 2;
            float v[4];
            v[0] = acc[mt][nt][0] + bias[c];
            v[1] = acc[mt][nt][1] + bias[c + 1];
            v[2] = acc[mt][nt][2] + bias[c];
            v[3] = acc[mt][nt][3] + bias[c + 1];
            #pragma unroll
            for (int e = 0; e < 4; e++) {
                int row = r0 + (e >> 1) * 8;
                int col = c + (e & 1);
                size_t idx = (size_t)row * N + col;
                if (Cf) {
                    Cf[idx] = v[e];
                } else if (z == 2) {
                    C2f[idx] = __float2half_rn(v[e]);
                } else {
                    bf16 hh = __float2bfloat16(v[e]);
                    Ch[idx] = hh;
                    Cl[idx] = __float2bfloat16(v[e] - __bfloat162float(hh));
                }
            }
        }
    }
}

// ---------------------------------------------------------------------------
// Flash attention, register-resident FA2.
// S = Q K^T in bf16x3 (3 mma terms). P·V in fp16: P hi/lo fp16 (2 terms),
// V single fp16. Br=128, Bc=64, hd=128, 256 threads.
// ---------------------------------------------------------------------------
#define FBR 128
#define FBC 64
#define FP  136
#define FQ_SZ (FBR * FP * 2)          // 34816
#define FKV_SZ (FBC * FP * 2)         // 17408
#define F_QH 0
#define F_QL (F_QH + FQ_SZ)
#define F_ST0 (F_QL + FQ_SZ)          // 69632
#define F_STG (3 * FKV_SZ)            // 52224 per stage (Kh, Kl, Vf)
#define F_KH(st) (F_ST0 + (st) * F_STG)
#define F_KL(st) (F_KH(st) + FKV_SZ)
#define F_V(st)  (F_KL(st) + FKV_SZ)
#define FSMEM (F_ST0 + 2 * F_STG)     // 174080

__global__ __launch_bounds__(256) void flash_bf16(
    const bf16* __restrict__ Qh, const bf16* __restrict__ Ql,
    const bf16* __restrict__ Kh, const bf16* __restrict__ Kl,
    const __half* __restrict__ Vf,
    const uint32_t* __restrict__ maskp,
    bf16* __restrict__ Oh, bf16* __restrict__ Ol)
{
    extern __shared__ char sm[];
    const int tid = threadIdx.x;
    const int l   = tid & 31;
    const int wid = tid >> 5;
    const int g   = l >> 2;
    const int t   = l & 3;
    const int wm  = wid * 16;
    const int bh  = blockIdx.y;
    const int q0  = blockIdx.x * FBR;
    const int b   = bh >> 4;
    const int h   = bh & 15;
    const float NEG_INF = __int_as_float(0xff800000);
    const float SCALE = 0.08838834764831845f;

    // load Q tile (128 x 128 hi/lo)
    {
        const size_t qb = ((size_t)(b * SEQ + q0)) * DMODEL + (size_t)h * HDIM;
        #pragma unroll
        for (int j = 0; j < 8; j++) {
            int u = tid + j * 256;
            int r = u >> 4, c8 = (u & 15) * 8;
            size_t gp = qb + (size_t)r * DMODEL + c8;
            *(uint4*)(sm + F_QH + (r * FP + c8) * 2) = *(const uint4*)(Qh + gp);
            *(uint4*)(sm + F_QL + (r * FP + c8) * 2) = *(const uint4*)(Ql + gp);
        }
    }

    auto issue_kv = [&](int kt, int st) {
        const size_t kb = ((size_t)(b * SEQ + kt * FBC)) * DMODEL + (size_t)h * HDIM;
        char* KH = sm + F_KH(st); char* KL = sm + F_KL(st); char* VV = sm + F_V(st);
        #pragma unroll
        for (int j = 0; j < 4; j++) {
            int u = tid + j * 256;
            int r = u >> 4, c8 = (u & 15) * 8;
            size_t gp = kb + (size_t)r * DMODEL + c8;
            int so = (r * FP + c8) * 2;
            cp16(KH + so, Kh + gp);
            cp16(KL + so, Kl + gp);
            cp16(VV + so, Vf + gp);
        }
    };

    issue_kv(0, 0); cp_commit();
    issue_kv(1, 1); cp_commit();

    float m0r = NEG_INF, m1r = NEG_INF, l0r = 0.f, l1r = 0.f;
    float oacc[16][4];
    #pragma unroll
    for (int nt = 0; nt < 16; nt++)
        #pragma unroll
        for (int q = 0; q < 4; q++) oacc[nt][q] = 0.f;

    const int NT = SEQ / FBC;   // 32
    const size_t mrow0 = ((size_t)b * SEQ + q0 + wm + g) * (SEQ / 32);
    const size_t mrow1 = mrow0 + 8 * (SEQ / 32);

    for (int kt = 0; kt < NT; kt++) {
        asm volatile("cp.async.wait_group 1;");
        __syncthreads();
        const int st = kt & 1;
        const char* KH = sm + F_KH(st); const char* KL = sm + F_KL(st);
        const char* VV = sm + F_V(st);

        // mask words (independent of mma; hoisted)
        const uint32_t w00 = maskp[mrow0 + kt * 2];
        const uint32_t w01 = maskp[mrow0 + kt * 2 + 1];
        const uint32_t w10 = maskp[mrow1 + kt * 2];
        const uint32_t w11 = maskp[mrow1 + kt * 2 + 1];

        // ---- S = Q K^T (bf16x3), warp tile 16m x 64n ----
        float sacc[8][4];
        #pragma unroll
        for (int nt = 0; nt < 8; nt++)
            #pragma unroll
            for (int q = 0; q < 4; q++) sacc[nt][q] = 0.f;

        #pragma unroll
        for (int ks = 0; ks < 8; ks++) {
            uint32_t qh4[4], ql4[4];
            int qoff = ((wm + (l & 15)) * FP + ks * 16 + ((l & 16) >> 1)) * 2;
            ldsm_x4(qh4, sm + F_QH + qoff);
            ldsm_x4(ql4, sm + F_QL + qoff);
            #pragma unroll
            for (int q = 0; q < 4; q++) {
                uint32_t kh4[4], kl4[4];
                int nr = q * 16 + (l & 7) + ((l & 16) >> 1);
                int kc = ks * 16 + (l & 8);
                int off = (nr * FP + kc) * 2;
                ldsm_x4(kh4, KH + off);
                ldsm_x4(kl4, KL + off);
                #pragma unroll
                for (int half = 0; half < 2; half++) {
                    const uint32_t* bhp = &kh4[half * 2];
                    const uint32_t* blp = &kl4[half * 2];
                    float* s = sacc[q * 2 + half];
                    mma_bf16(s, qh4, bhp);
                    mma_bf16(s, qh4, blp);
                    mma_bf16(s, ql4, bhp);
                }
            }
        }

        // ---- scale + mask + row max ----
        float mx0 = NEG_INF, mx1 = NEG_INF;
        #pragma unroll
        for (int nt = 0; nt < 8; nt++) {
            const int c  = nt * 8 + 2 * t;
            const int sh = c & 31;
            const uint32_t wr0 = (nt < 4) ? w00 : w01;
            const uint32_t wr1 = (nt < 4) ? w10 : w11;
            float v0 = sacc[nt][0] * SCALE; if (!((wr0 >> sh) & 1))       v0 = NEG_INF;
            float v1 = sacc[nt][1] * SCALE; if (!((wr0 >> (sh + 1)) & 1)) v1 = NEG_INF;
            float v2 = sacc[nt][2] * SCALE; if (!((wr1 >> sh) & 1))       v2 = NEG_INF;
            float v3 = sacc[nt][3] * SCALE; if (!((wr1 >> (sh + 1)) & 1)) v3 = NEG_INF;
            sacc[nt][0] = v0; sacc[nt][1] = v1; sacc[nt][2] = v2; sacc[nt][3] = v3;
            mx0 = fmaxf(mx0, fmaxf(v0, v1));
            mx1 = fmaxf(mx1, fmaxf(v2, v3));
        }
        mx0 = fmaxf(mx0, __shfl_xor_sync(0xffffffffu, mx0, 1));
        mx0 = fmaxf(mx0, __shfl_xor_sync(0xffffffffu, mx0, 2));
        mx1 = fmaxf(mx1, __shfl_xor_sync(0xffffffffu, mx1, 1));
        mx1 = fmaxf(mx1, __shfl_xor_sync(0xffffffffu, mx1, 2));

        const float mn0 = fmaxf(m0r, mx0);
        const float mn1 = fmaxf(m1r, mx1);
        const float al0 = (m0r == NEG_INF) ? 0.f : __expf(m0r - mn0);
        const float al1 = (m1r == NEG_INF) ? 0.f : __expf(m1r - mn1);
        m0r = mn0; m1r = mn1;

        // ---- P = exp(S - m), rowsum ----
        float sum0 = 0.f, sum1 = 0.f;
        #pragma unroll
        for (int nt = 0; nt < 8; nt++) {
            float p0 = __expf(sacc[nt][0] - mn0);
            float p1 = __expf(sacc[nt][1] - mn0);
            float p2 = __expf(sacc[nt][2] - mn1);
            float p3 = __expf(sacc[nt][3] - mn1);
            sacc[nt][0] = p0; sacc[nt][1] = p1; sacc[nt][2] = p2; sacc[nt][3] = p3;
            sum0 += p0 + p1;
            sum1 += p2 + p3;
        }
        sum0 += __shfl_xor_sync(0xffffffffu, sum0, 1);
        sum0 += __shfl_xor_sync(0xffffffffu, sum0, 2);
        sum1 += __shfl_xor_sync(0xffffffffu, sum1, 1);
        sum1 += __shfl_xor_sync(0xffffffffu, sum1, 2);
        l0r = l0r * al0 + sum0;
        l1r = l1r * al1 + sum1;

        // ---- rescale O (skip when alpha == 1 exactly: no new max) ----
        if (!(al0 == 1.f && al1 == 1.f)) {
            #pragma unroll
            for (int nt = 0; nt < 16; nt++) {
                oacc[nt][0] *= al0; oacc[nt][1] *= al0;
                oacc[nt][2] *= al1; oacc[nt][3] *= al1;
            }
        }

        // ---- O += P V : P hi/lo fp16 (2 mma), V single fp16 ----
        #pragma unroll
        for (int s = 0; s < 4; s++) {
            uint32_t pah[4], pal[4];
            {
                const float* c0 = sacc[2 * s];
                const float* c1 = sacc[2 * s + 1];
                pah[0] = pack_f16x2(c0[0], c0[1]);
                pah[1] = pack_f16x2(c0[2], c0[3]);
                pah[2] = pack_f16x2(c1[0], c1[1]);
                pah[3] = pack_f16x2(c1[2], c1[3]);
                __half2 h2;
                h2 = *(__half2*)&pah[0];
                pal[0] = pack_f16x2(c0[0] - __half2float(h2.x), c0[1] - __half2float(h2.y));
                h2 = *(__half2*)&pah[1];
                pal[1] = pack_f16x2(c0[2] - __half2float(h2.x), c0[3] - __half2float(h2.y));
                h2 = *(__half2*)&pah[2];
                pal[2] = pack_f16x2(c1[0] - __half2float(h2.x), c1[1] - __half2float(h2.y));
                h2 = *(__half2*)&pah[3];
                pal[3] = pack_f16x2(c1[2] - __half2float(h2.x), c1[3] - __half2float(h2.y));
            }
            #pragma unroll
            for (int q = 0; q < 8; q++) {
                uint32_t vh4[4];
                int vr = s * 16 + (l & 15);
                int vc = q * 16 + ((l & 16) >> 1);
                ldsm_x4t(vh4, VV + (vr * FP + vc) * 2);
                #pragma unroll
                for (int half = 0; half < 2; half++) {
                    const uint32_t* bhp = &vh4[half * 2];
                    float* o = oacc[q * 2 + half];
                    mma_f16(o, pah, bhp);
                    mma_f16(o, pal, bhp);
                }
            }
        }

        __syncthreads();
        if (kt + 2 < NT) issue_kv(kt + 2, st);
        cp_commit();
    }

    // ---- epilogue ----
    {
        const float inv0 = 1.f / l0r;
        const float inv1 = 1.f / l1r;
        const int r0 = q0 + wm + g;
        const int r1 = r0 + 8;
        const size_t b0 = ((size_t)(b * SEQ + r0)) * DMODEL + (size_t)h * HDIM;
        const size_t b1 = ((size_t)(b * SEQ + r1)) * DMODEL + (size_t)h * HDIM;
        #pragma unroll
        for (int nt = 0; nt < 16; nt++) {
            const int c = nt * 8 + 2 * t;
            float v00 = oacc[nt][0] * inv0, v01 = oacc[nt][1] * inv0;
            float v10 = oacc[nt][2] * inv1, v11 = oacc[nt][3] * inv1;
            uint32_t h0 = pack_bf16x2(v00, v01);
            uint32_t h1 = pack_bf16x2(v10, v11);
            __nv_bfloat162 hh;
            hh = *(__nv_bfloat162*)&h0;
            uint32_t l0 = pack_bf16x2(v00 - __bfloat162float(hh.x), v01 - __bfloat162float(hh.y));
            hh = *(__nv_bfloat162*)&h1;
            uint32_t l1 = pack_bf16x2(v10 - __bfloat162float(hh.x), v11 - __bfloat162float(hh.y));
            *(uint32_t*)(Oh + b0 + c) = h0;
            *(uint32_t*)(Ol + b0 + c) = l0;
            *(uint32_t*)(Oh + b1 + c) = h1;
            *(uint32_t*)(Ol + b1 + c) = l1;
        }
    }
}

// ---------------------------------------------------------------------------
// Launch
// ---------------------------------------------------------------------------
extern "C" void kernel_launch(void* const* d_in, const int* in_sizes, int n_in,
                              void* d_out, int out_size)
{
    const float* x    = (const float*)d_in[0];
    const int*   mask = (const int*)  d_in[1];
    const float* Wq   = (const float*)d_in[2];
    const float* bq   = (const float*)d_in[3];
    const float* Wk   = (const float*)d_in[4];
    const float* bk   = (const float*)d_in[5];
    const float* Wv   = (const float*)d_in[6];
    const float* bv   = (const float*)d_in[7];
    const float* Wo   = (const float*)d_in[8];
    const float* bo   = (const float*)d_in[9];
    float* out = (float*)d_out;

    bf16 *pxh, *pxl, *pWh, *pWl, *pQh, *pQl, *pKh, *pKl, *pAh, *pAl;
    __half* pVf;
    uint32_t* pMp;
    cudaGetSymbolAddress((void**)&pxh, g_xh);
    cudaGetSymbolAddress((void**)&pxl, g_xl);
    cudaGetSymbolAddress((void**)&pWh, g_Wh);
    cudaGetSymbolAddress((void**)&pWl, g_Wl);
    cudaGetSymbolAddress((void**)&pQh, g_Qh);
    cudaGetSymbolAddress((void**)&pQl, g_Ql);
    cudaGetSymbolAddress((void**)&pKh, g_Kh);
    cudaGetSymbolAddress((void**)&pKl, g_Kl);
    cudaGetSymbolAddress((void**)&pVf, g_Vf);
    cudaGetSymbolAddress((void**)&pAh, g_Ah);
    cudaGetSymbolAddress((void**)&pAl, g_Al);
    cudaGetSymbolAddress((void**)&pMp, g_maskp);

    cudaFuncSetAttribute(gemm_bf16x3, cudaFuncAttributeMaxDynamicSharedMemorySize, GSMEM);
    cudaFuncSetAttribute(flash_bf16, cudaFuncAttributeMaxDynamicSharedMemorySize, FSMEM);

    const int n4x = MROWS * DMODEL / 4;
    const int n4w = (int)(WSZ / 4);
    const int nw  = BATCH * SEQ * (SEQ / 32);

    split_kernel<<<(n4x + 255) / 256, 256>>>(x, pxh, pxl, n4x);
    pack_mask<<<(nw + 255) / 256, 256>>>(mask, pMp, nw);
    split_w4<<<dim3(n4w / 256, 4), 256>>>(Wq, Wk, Wv, Wo, pWh, pWl);

    // Fused Q/K/V projection: grid.z selects weight slot + output
    gemm_bf16x3<<<dim3(DMODEL / 128, MROWS / 128, 3), 256, GSMEM>>>(
        pxh, pxl, pWh, pWl, bq, bk, bv,
        pQh, pQl, pKh, pKl, pVf, nullptr, 0);

    flash_bf16<<<dim3(SEQ / FBR, BATCH * NHEAD), 256, FSMEM>>>(
        pQh, pQl, pKh, pKl, pVf, pMp, pAh, pAl);

    // Output projection (weight slot 3, fp32 out)
    gemm_bf16x3<<<dim3(DMODEL / 128, MROWS / 128, 1), 256, GSMEM>>>(
        pAh, pAl, pWh, pWl, bo, bo, bo,
        nullptr, nullptr, nullptr, nullptr, nullptr, out, 3);
}

// round 15
// speedup vs baseline: 5.4439x; 1.3045x over previous
#include <cuda_runtime.h>
#include <cuda_bf16.h>
#include <cuda_fp16.h>
#include <math.h>
#include <stdint.h>

#define BATCH  4
#define SEQ    2048
#define DMODEL 2048
#define NHEAD  16
#define HDIM   128
#define MROWS  (BATCH * SEQ)   // 8192
#define WSZ    ((size_t)DMODEL * DMODEL)

typedef __nv_bfloat16 bf16;
typedef __half f16;

// ---------------------------------------------------------------------------
// Scratch (device globals; no runtime allocation allowed). All fp16 now.
// ---------------------------------------------------------------------------
__device__ f16 g_xh[(size_t)MROWS * DMODEL];
__device__ f16 g_xl[(size_t)MROWS * DMODEL];
__device__ f16 g_Wf[4 * WSZ];                 // 4 weight slots, single fp16
__device__ f16 g_Qh[(size_t)MROWS * DMODEL];  // Q hi/lo (exact)
__device__ f16 g_Ql[(size_t)MROWS * DMODEL];
__device__ f16 g_Kf[(size_t)MROWS * DMODEL];  // K single fp16
__device__ f16 g_Vf[(size_t)MROWS * DMODEL];  // V single fp16
__device__ f16 g_Ah[(size_t)MROWS * DMODEL];  // attn out hi/lo (exact)
__device__ f16 g_Al[(size_t)MROWS * DMODEL];
__device__ uint32_t g_maskp[(size_t)BATCH * SEQ * (SEQ / 32)];

// ---------------------------------------------------------------------------
// Helpers
// ---------------------------------------------------------------------------
__device__ __forceinline__ void ldsm_x4(uint32_t r[4], const void* p) {
    uint32_t a = (uint32_t)__cvta_generic_to_shared(p);
    asm volatile("ldmatrix.sync.aligned.m8n8.x4.shared.b16 {%0,%1,%2,%3}, [%4];"
                 : "=r"(r[0]), "=r"(r[1]), "=r"(r[2]), "=r"(r[3]) : "r"(a));
}
__device__ __forceinline__ void ldsm_x4t(uint32_t r[4], const void* p) {
    uint32_t a = (uint32_t)__cvta_generic_to_shared(p);
    asm volatile("ldmatrix.sync.aligned.m8n8.x4.trans.shared.b16 {%0,%1,%2,%3}, [%4];"
                 : "=r"(r[0]), "=r"(r[1]), "=r"(r[2]), "=r"(r[3]) : "r"(a));
}
__device__ __forceinline__ void mma_f16(float c[4], const uint32_t a[4], const uint32_t b[2]) {
    asm volatile(
        "mma.sync.aligned.m16n8k16.row.col.f32.f16.f16.f32 "
        "{%0,%1,%2,%3}, {%4,%5,%6,%7}, {%8,%9}, {%0,%1,%2,%3};"
        : "+f"(c[0]), "+f"(c[1]), "+f"(c[2]), "+f"(c[3])
        : "r"(a[0]), "r"(a[1]), "r"(a[2]), "r"(a[3]), "r"(b[0]), "r"(b[1]));
}
__device__ __forceinline__ void cp16(void* s, const void* g) {
    uint32_t sa = (uint32_t)__cvta_generic_to_shared(s);
    asm volatile("cp.async.cg.shared.global [%0], [%1], 16;" :: "r"(sa), "l"(g));
}
__device__ __forceinline__ void cp_commit() { asm volatile("cp.async.commit_group;"); }

__device__ __forceinline__ uint32_t pack_f16x2(float lo, float hi) {
    __half2 h2 = __floats2half2_rn(lo, hi);
    return *(uint32_t*)&h2;
}

// ---------------------------------------------------------------------------
// Split fp32 -> (fp16 hi, fp16 lo): exact to ~2^-22
// ---------------------------------------------------------------------------
__global__ __launch_bounds__(256) void split_kernel(
    const float* __restrict__ in, f16* __restrict__ hi, f16* __restrict__ lo, int n4)
{
    int i = blockIdx.x * 256 + threadIdx.x;
    if (i >= n4) return;
    float4 f = ((const float4*)in)[i];
    f16 h0 = __float2half_rn(f.x); f16 l0 = __float2half_rn(f.x - __half2float(h0));
    f16 h1 = __float2half_rn(f.y); f16 l1 = __float2half_rn(f.y - __half2float(h1));
    f16 h2 = __float2half_rn(f.z); f16 l2 = __float2half_rn(f.z - __half2float(h2));
    f16 h3 = __float2half_rn(f.w); f16 l3 = __float2half_rn(f.w - __half2float(h3));
    __half2 a, b;
    a = __halves2half2(h0, h1); b = __halves2half2(h2, h3);
    ((__half2*)hi)[2 * i] = a; ((__half2*)hi)[2 * i + 1] = b;
    a = __halves2half2(l0, l1); b = __halves2half2(l2, l3);
    ((__half2*)lo)[2 * i] = a; ((__half2*)lo)[2 * i + 1] = b;
}

// ---------------------------------------------------------------------------
// Convert all 4 weights into single-fp16 slots. grid (WSZ/4/256, 4)
// ---------------------------------------------------------------------------
__global__ __launch_bounds__(256) void conv_w4(
    const float* __restrict__ w0, const float* __restrict__ w1,
    const float* __restrict__ w2, const float* __restrict__ w3,
    f16* __restrict__ dst)
{
    const int widx = blockIdx.y;
    const float* src = (widx == 0) ? w0 : (widx == 1) ? w1 : (widx == 2) ? w2 : w3;
    f16* dp = dst + (size_t)widx * WSZ;
    int i = blockIdx.x * 256 + threadIdx.x;
    float4 f = ((const float4*)src)[i];
    ((__half2*)dp)[2 * i]     = __floats2half2_rn(f.x, f.y);
    ((__half2*)dp)[2 * i + 1] = __floats2half2_rn(f.z, f.w);
}

// ---------------------------------------------------------------------------
// Pack int32 mask into bitfield
// ---------------------------------------------------------------------------
__global__ __launch_bounds__(256) void pack_mask(
    const int* __restrict__ mask, uint32_t* __restrict__ out, int nw)
{
    int i = blockIdx.x * 256 + threadIdx.x;
    if (i >= nw) return;
    const int4* p = (const int4*)mask + (size_t)i * 8;
    uint32_t w = 0;
    #pragma unroll
    for (int j = 0; j < 8; j++) {
        int4 v = p[j];
        w |= (v.x != 0 ? 1u : 0u) << (j * 4 + 0);
        w |= (v.y != 0 ? 1u : 0u) << (j * 4 + 1);
        w |= (v.z != 0 ? 1u : 0u) << (j * 4 + 2);
        w |= (v.w != 0 ? 1u : 0u) << (j * 4 + 3);
    }
    out[i] = w;
}

// ---------------------------------------------------------------------------
// GEMM fp16 2-term: C = Ah*W + Al*W + bias (fp32 accum)
// A [M,K] hi/lo fp16, W [K,N] single fp16 (slot wslot0+z).
//   QKV fused: grid.z=3; z0 -> Q hi/lo, z1 -> K fp16, z2 -> V fp16.
//   O: grid.z=1, wslot0=3, Cf fp32.
// Tiles 128x128x32, 256 threads (8 warps, 32m x 64n), cp.async dbuf.
// ---------------------------------------------------------------------------
#define GBK 32
#define AP  40
#define BP  136
#define A_BUF (128 * AP * 2)            // 10240
#define B_BUF (GBK * BP * 2)            // 8704
#define GSTG  (2 * A_BUF + B_BUF)       // 29184
#define GS_AH(st) ((st) * GSTG)
#define GS_AL(st) ((st) * GSTG + A_BUF)
#define GS_B(st)  ((st) * GSTG + 2 * A_BUF)
#define GSMEM (2 * GSTG)                // 58368

__global__ __launch_bounds__(256, 2) void gemm_f16(
    const f16* __restrict__ Agh, const f16* __restrict__ Agl,
    const f16* __restrict__ Wf4,
    const float* __restrict__ b0, const float* __restrict__ b1, const float* __restrict__ b2,
    f16* __restrict__ C0h, f16* __restrict__ C0l,
    f16* __restrict__ C1f, f16* __restrict__ C2f,
    float* __restrict__ Cf, int wslot0)
{
    extern __shared__ char sm[];
    const int z = blockIdx.z;
    const f16* Bg = Wf4 + (size_t)(wslot0 + z) * WSZ;
    const float* bias = (z == 0) ? b0 : (z == 1) ? b1 : b2;

    const int tid = threadIdx.x;
    const int l   = tid & 31;
    const int wid = tid >> 5;
    const int wm  = (wid & 3) * 32;
    const int wn  = (wid >> 2) * 64;
    const int m0  = blockIdx.y * 128;
    const int n0  = blockIdx.x * 128;
    const int K = DMODEL, N = DMODEL;

    float acc[2][8][4];
    #pragma unroll
    for (int mt = 0; mt < 2; mt++)
        #pragma unroll
        for (int nt = 0; nt < 8; nt++)
            #pragma unroll
            for (int q = 0; q < 4; q++) acc[mt][nt][q] = 0.f;

    auto issue = [&](int k0, int st) {
        char* pAh = sm + GS_AH(st);
        char* pAl = sm + GS_AL(st);
        char* pB  = sm + GS_B(st);
        #pragma unroll
        for (int j = 0; j < 2; j++) {
            int u  = tid + j * 256;
            int r  = u >> 2;
            int c8 = (u & 3) * 8;
            size_t ga = (size_t)(m0 + r) * K + k0 + c8;
            cp16(pAh + (r * AP + c8) * 2, Agh + ga);
            cp16(pAl + (r * AP + c8) * 2, Agl + ga);
            int rb  = u >> 4;
            int cb8 = (u & 15) * 8;
            size_t gb = (size_t)(k0 + rb) * N + n0 + cb8;
            cp16(pB + (rb * BP + cb8) * 2, Bg + gb);
        }
    };

    issue(0, 0); cp_commit();
    asm volatile("cp.async.wait_group 0;");
    __syncthreads();

    int st = 0;
    for (int k0 = 0; k0 < K; k0 += GBK) {
        const bool nxt = (k0 + GBK) < K;
        if (nxt) { issue(k0 + GBK, st ^ 1); cp_commit(); }

        char* pAh = sm + GS_AH(st);
        char* pAl = sm + GS_AL(st);
        char* pB  = sm + GS_B(st);

        #pragma unroll
        for (int ks = 0; ks < 2; ks++) {
            uint32_t ah[2][4], al[2][4];
            #pragma unroll
            for (int mt = 0; mt < 2; mt++) {
                int off = ((wm + mt * 16 + (l & 15)) * AP + ks * 16 + ((l & 16) >> 1)) * 2;
                ldsm_x4(ah[mt], pAh + off);
                ldsm_x4(al[mt], pAl + off);
            }
            uint32_t bb[4][4];
            #pragma unroll
            for (int q = 0; q < 4; q++) {
                int off = ((ks * 16 + (l & 15)) * BP + wn + q * 16 + ((l & 16) >> 1)) * 2;
                ldsm_x4t(bb[q], pB + off);
            }
            #pragma unroll
            for (int mt = 0; mt < 2; mt++)
                #pragma unroll
                for (int nt = 0; nt < 8; nt++) {
                    const uint32_t* bp = &bb[nt >> 1][(nt & 1) * 2];
                    mma_f16(acc[mt][nt], ah[mt], bp);
                    mma_f16(acc[mt][nt], al[mt], bp);
                }
        }
        if (nxt) asm volatile("cp.async.wait_group 0;");
        __syncthreads();
        st ^= 1;
    }

    #pragma unroll
    for (int mt = 0; mt < 2; mt++) {
        #pragma unroll
        for (int nt = 0; nt < 8; nt++) {
            int r0 = m0 + wm + mt * 16 + (l >> 2);
            int c  = n0 + wn + nt * 8 + (l & 3) * 2;
            float v[4];
            v[0] = acc[mt][nt][0] + bias[c];
            v[1] = acc[mt][nt][1] + bias[c + 1];
            v[2] = acc[mt][nt][2] + bias[c];
            v[3] = acc[mt][nt][3] + bias[c + 1];
            #pragma unroll
            for (int e = 0; e < 4; e++) {
                int row = r0 + (e >> 1) * 8;
                int col = c + (e & 1);
                size_t idx = (size_t)row * N + col;
                if (Cf) {
                    Cf[idx] = v[e];
                } else if (z == 0) {
                    f16 hh = __float2half_rn(v[e]);
                    C0h[idx] = hh;
                    C0l[idx] = __float2half_rn(v[e] - __half2float(hh));
                } else if (z == 1) {
                    C1f[idx] = __float2half_rn(v[e]);
                } else {
                    C2f[idx] = __float2half_rn(v[e]);
                }
            }
        }
    }
}

// ---------------------------------------------------------------------------
// Flash attention, register-resident FA2 (all fp16 mma).
// S = Qh*K + Ql*K (Q hi/lo exact, K single). P·V: P hi/lo + V single.
// Br=128, Bc=64, hd=128, 256 threads.
// ---------------------------------------------------------------------------
#define FBR 128
#define FBC 64
#define FP  136
#define FQ_SZ (FBR * FP * 2)          // 34816
#define FKV_SZ (FBC * FP * 2)         // 17408
#define F_QH 0
#define F_QL (F_QH + FQ_SZ)
#define F_ST0 (F_QL + FQ_SZ)          // 69632
#define F_STG (2 * FKV_SZ)            // 34816 per stage (K, V)
#define F_K(st) (F_ST0 + (st) * F_STG)
#define F_V(st) (F_K(st) + FKV_SZ)
#define FSMEM (F_ST0 + 2 * F_STG)     // 139264

__global__ __launch_bounds__(256) void flash_f16(
    const f16* __restrict__ Qh, const f16* __restrict__ Ql,
    const f16* __restrict__ Kf, const f16* __restrict__ Vf,
    const uint32_t* __restrict__ maskp,
    f16* __restrict__ Oh, f16* __restrict__ Ol)
{
    extern __shared__ char sm[];
    const int tid = threadIdx.x;
    const int l   = tid & 31;
    const int wid = tid >> 5;
    const int g   = l >> 2;
    const int t   = l & 3;
    const int wm  = wid * 16;
    const int bh  = blockIdx.y;
    const int q0  = blockIdx.x * FBR;
    const int b   = bh >> 4;
    const int h   = bh & 15;
    const float NEG_INF = __int_as_float(0xff800000);
    const float SCALE = 0.08838834764831845f;

    // load Q tile (128 x 128 hi/lo)
    {
        const size_t qb = ((size_t)(b * SEQ + q0)) * DMODEL + (size_t)h * HDIM;
        #pragma unroll
        for (int j = 0; j < 8; j++) {
            int u = tid + j * 256;
            int r = u >> 4, c8 = (u & 15) * 8;
            size_t gp = qb + (size_t)r * DMODEL + c8;
            *(uint4*)(sm + F_QH + (r * FP + c8) * 2) = *(const uint4*)(Qh + gp);
            *(uint4*)(sm + F_QL + (r * FP + c8) * 2) = *(const uint4*)(Ql + gp);
        }
    }

    auto issue_kv = [&](int kt, int st) {
        const size_t kb = ((size_t)(b * SEQ + kt * FBC)) * DMODEL + (size_t)h * HDIM;
        char* KK = sm + F_K(st); char* VV = sm + F_V(st);
        #pragma unroll
        for (int j = 0; j < 4; j++) {
            int u = tid + j * 256;
            int r = u >> 4, c8 = (u & 15) * 8;
            size_t gp = kb + (size_t)r * DMODEL + c8;
            int so = (r * FP + c8) * 2;
            cp16(KK + so, Kf + gp);
            cp16(VV + so, Vf + gp);
        }
    };

    issue_kv(0, 0); cp_commit();
    issue_kv(1, 1); cp_commit();

    float m0r = NEG_INF, m1r = NEG_INF, l0r = 0.f, l1r = 0.f;
    float oacc[16][4];
    #pragma unroll
    for (int nt = 0; nt < 16; nt++)
        #pragma unroll
        for (int q = 0; q < 4; q++) oacc[nt][q] = 0.f;

    const int NT = SEQ / FBC;   // 32
    const size_t mrow0 = ((size_t)b * SEQ + q0 + wm + g) * (SEQ / 32);
    const size_t mrow1 = mrow0 + 8 * (SEQ / 32);

    for (int kt = 0; kt < NT; kt++) {
        asm volatile("cp.async.wait_group 1;");
        __syncthreads();
        const int st = kt & 1;
        const char* KK = sm + F_K(st);
        const char* VV = sm + F_V(st);

        const uint32_t w00 = maskp[mrow0 + kt * 2];
        const uint32_t w01 = maskp[mrow0 + kt * 2 + 1];
        const uint32_t w10 = maskp[mrow1 + kt * 2];
        const uint32_t w11 = maskp[mrow1 + kt * 2 + 1];

        // ---- S = Q K^T (fp16 2-term), warp tile 16m x 64n ----
        float sacc[8][4];
        #pragma unroll
        for (int nt = 0; nt < 8; nt++)
            #pragma unroll
            for (int q = 0; q < 4; q++) sacc[nt][q] = 0.f;

        #pragma unroll
        for (int ks = 0; ks < 8; ks++) {
            uint32_t qh4[4], ql4[4];
            int qoff = ((wm + (l & 15)) * FP + ks * 16 + ((l & 16) >> 1)) * 2;
            ldsm_x4(qh4, sm + F_QH + qoff);
            ldsm_x4(ql4, sm + F_QL + qoff);
            #pragma unroll
            for (int q = 0; q < 4; q++) {
                uint32_t kk4[4];
                int nr = q * 16 + (l & 7) + ((l & 16) >> 1);
                int kc = ks * 16 + (l & 8);
                ldsm_x4(kk4, KK + (nr * FP + kc) * 2);
                #pragma unroll
                for (int half = 0; half < 2; half++) {
                    const uint32_t* bp = &kk4[half * 2];
                    float* s = sacc[q * 2 + half];
                    mma_f16(s, qh4, bp);
                    mma_f16(s, ql4, bp);
                }
            }
        }

        // ---- scale + mask + row max ----
        float mx0 = NEG_INF, mx1 = NEG_INF;
        #pragma unroll
        for (int nt = 0; nt < 8; nt++) {
            const int c  = nt * 8 + 2 * t;
            const int sh = c & 31;
            const uint32_t wr0 = (nt < 4) ? w00 : w01;
            const uint32_t wr1 = (nt < 4) ? w10 : w11;
            float v0 = sacc[nt][0] * SCALE; if (!((wr0 >> sh) & 1))       v0 = NEG_INF;
            float v1 = sacc[nt][1] * SCALE; if (!((wr0 >> (sh + 1)) & 1)) v1 = NEG_INF;
            float v2 = sacc[nt][2] * SCALE; if (!((wr1 >> sh) & 1))       v2 = NEG_INF;
            float v3 = sacc[nt][3] * SCALE; if (!((wr1 >> (sh + 1)) & 1)) v3 = NEG_INF;
            sacc[nt][0] = v0; sacc[nt][1] = v1; sacc[nt][2] = v2; sacc[nt][3] = v3;
            mx0 = fmaxf(mx0, fmaxf(v0, v1));
            mx1 = fmaxf(mx1, fmaxf(v2, v3));
        }
        mx0 = fmaxf(mx0, __shfl_xor_sync(0xffffffffu, mx0, 1));
        mx0 = fmaxf(mx0, __shfl_xor_sync(0xffffffffu, mx0, 2));
        mx1 = fmaxf(mx1, __shfl_xor_sync(0xffffffffu, mx1, 1));
        mx1 = fmaxf(mx1, __shfl_xor_sync(0xffffffffu, mx1, 2));

        const float mn0 = fmaxf(m0r, mx0);
        const float mn1 = fmaxf(m1r, mx1);
        const float al0 = (m0r == NEG_INF) ? 0.f : __expf(m0r - mn0);
        const float al1 = (m1r == NEG_INF) ? 0.f : __expf(m1r - mn1);
        m0r = mn0; m1r = mn1;

        // ---- P = exp(S - m), rowsum ----
        float sum0 = 0.f, sum1 = 0.f;
        #pragma unroll
        for (int nt = 0; nt < 8; nt++) {
            float p0 = __expf(sacc[nt][0] - mn0);
            float p1 = __expf(sacc[nt][1] - mn0);
            float p2 = __expf(sacc[nt][2] - mn1);
            float p3 = __expf(sacc[nt][3] - mn1);
            sacc[nt][0] = p0; sacc[nt][1] = p1; sacc[nt][2] = p2; sacc[nt][3] = p3;
            sum0 += p0 + p1;
            sum1 += p2 + p3;
        }
        sum0 += __shfl_xor_sync(0xffffffffu, sum0, 1);
        sum0 += __shfl_xor_sync(0xffffffffu, sum0, 2);
        sum1 += __shfl_xor_sync(0xffffffffu, sum1, 1);
        sum1 += __shfl_xor_sync(0xffffffffu, sum1, 2);
        l0r = l0r * al0 + sum0;
        l1r = l1r * al1 + sum1;

        // ---- rescale O (skip when alpha == 1 exactly) ----
        if (!(al0 == 1.f && al1 == 1.f)) {
            #pragma unroll
            for (int nt = 0; nt < 16; nt++) {
                oacc[nt][0] *= al0; oacc[nt][1] *= al0;
                oacc[nt][2] *= al1; oacc[nt][3] *= al1;
            }
        }

        // ---- O += P V : P hi/lo fp16, V single fp16 ----
        #pragma unroll
        for (int s = 0; s < 4; s++) {
            uint32_t pah[4], pal[4];
            {
                const float* c0 = sacc[2 * s];
                const float* c1 = sacc[2 * s + 1];
                pah[0] = pack_f16x2(c0[0], c0[1]);
                pah[1] = pack_f16x2(c0[2], c0[3]);
                pah[2] = pack_f16x2(c1[0], c1[1]);
                pah[3] = pack_f16x2(c1[2], c1[3]);
                __half2 h2;
                h2 = *(__half2*)&pah[0];
                pal[0] = pack_f16x2(c0[0] - __half2float(h2.x), c0[1] - __half2float(h2.y));
                h2 = *(__half2*)&pah[1];
                pal[1] = pack_f16x2(c0[2] - __half2float(h2.x), c0[3] - __half2float(h2.y));
                h2 = *(__half2*)&pah[2];
                pal[2] = pack_f16x2(c1[0] - __half2float(h2.x), c1[1] - __half2float(h2.y));
                h2 = *(__half2*)&pah[3];
                pal[3] = pack_f16x2(c1[2] - __half2float(h2.x), c1[3] - __half2float(h2.y));
            }
            #pragma unroll
            for (int q = 0; q < 8; q++) {
                uint32_t vh4[4];
                int vr = s * 16 + (l & 15);
                int vc = q * 16 + ((l & 16) >> 1);
                ldsm_x4t(vh4, VV + (vr * FP + vc) * 2);
                #pragma unroll
                for (int half = 0; half < 2; half++) {
                    const uint32_t* bp = &vh4[half * 2];
                    float* o = oacc[q * 2 + half];
                    mma_f16(o, pah, bp);
                    mma_f16(o, pal, bp);
                }
            }
        }

        __syncthreads();
        if (kt + 2 < NT) issue_kv(kt + 2, st);
        cp_commit();
    }

    // ---- epilogue: normalize, write hi/lo fp16 to [B,S,D] ----
    {
        const float inv0 = 1.f / l0r;
        const float inv1 = 1.f / l1r;
        const int r0 = q0 + wm + g;
        const int r1 = r0 + 8;
        const size_t b0 = ((size_t)(b * SEQ + r0)) * DMODEL + (size_t)h * HDIM;
        const size_t b1 = ((size_t)(b * SEQ + r1)) * DMODEL + (size_t)h * HDIM;
        #pragma unroll
        for (int nt = 0; nt < 16; nt++) {
            const int c = nt * 8 + 2 * t;
            float v00 = oacc[nt][0] * inv0, v01 = oacc[nt][1] * inv0;
            float v10 = oacc[nt][2] * inv1, v11 = oacc[nt][3] * inv1;
            uint32_t h0 = pack_f16x2(v00, v01);
            uint32_t h1 = pack_f16x2(v10, v11);
            __half2 hh;
            hh = *(__half2*)&h0;
            uint32_t l0 = pack_f16x2(v00 - __half2float(hh.x), v01 - __half2float(hh.y));
            hh = *(__half2*)&h1;
            uint32_t l1 = pack_f16x2(v10 - __half2float(hh.x), v11 - __half2float(hh.y));
            *(uint32_t*)(Oh + b0 + c) = h0;
            *(uint32_t*)(Ol + b0 + c) = l0;
            *(uint32_t*)(Oh + b1 + c) = h1;
            *(uint32_t*)(Ol + b1 + c) = l1;
        }
    }
}

// ---------------------------------------------------------------------------
// Launch
// ---------------------------------------------------------------------------
extern "C" void kernel_launch(void* const* d_in, const int* in_sizes, int n_in,
                              void* d_out, int out_size)
{
    const float* x    = (const float*)d_in[0];
    const int*   mask = (const int*)  d_in[1];
    const float* Wq   = (const float*)d_in[2];
    const float* bq   = (const float*)d_in[3];
    const float* Wk   = (const float*)d_in[4];
    const float* bk   = (const float*)d_in[5];
    const float* Wv   = (const float*)d_in[6];
    const float* bv   = (const float*)d_in[7];
    const float* Wo   = (const float*)d_in[8];
    const float* bo   = (const float*)d_in[9];
    float* out = (float*)d_out;

    f16 *pxh, *pxl, *pWf, *pQh, *pQl, *pKf, *pVf, *pAh, *pAl;
    uint32_t* pMp;
    cudaGetSymbolAddress((void**)&pxh, g_xh);
    cudaGetSymbolAddress((void**)&pxl, g_xl);
    cudaGetSymbolAddress((void**)&pWf, g_Wf);
    cudaGetSymbolAddress((void**)&pQh, g_Qh);
    cudaGetSymbolAddress((void**)&pQl, g_Ql);
    cudaGetSymbolAddress((void**)&pKf, g_Kf);
    cudaGetSymbolAddress((void**)&pVf, g_Vf);
    cudaGetSymbolAddress((void**)&pAh, g_Ah);
    cudaGetSymbolAddress((void**)&pAl, g_Al);
    cudaGetSymbolAddress((void**)&pMp, g_maskp);

    cudaFuncSetAttribute(gemm_f16, cudaFuncAttributeMaxDynamicSharedMemorySize, GSMEM);
    cudaFuncSetAttribute(flash_f16, cudaFuncAttributeMaxDynamicSharedMemorySize, FSMEM);

    const int n4x = MROWS * DMODEL / 4;
    const int n4w = (int)(WSZ / 4);
    const int nw  = BATCH * SEQ * (SEQ / 32);

    split_kernel<<<(n4x + 255) / 256, 256>>>(x, pxh, pxl, n4x);
    pack_mask<<<(nw + 255) / 256, 256>>>(mask, pMp, nw);
    conv_w4<<<dim3(n4w / 256, 4), 256>>>(Wq, Wk, Wv, Wo, pWf);

    // Fused Q/K/V projection
    gemm_f16<<<dim3(DMODEL / 128, MROWS / 128, 3), 256, GSMEM>>>(
        pxh, pxl, pWf, bq, bk, bv,
        pQh, pQl, pKf, pVf, nullptr, 0);

    flash_f16<<<dim3(SEQ / FBR, BATCH * NHEAD), 256, FSMEM>>>(
        pQh, pQl, pKf, pVf, pMp, pAh, pAl);

    // Output projection (weight slot 3, fp32 out)
    gemm_f16<<<dim3(DMODEL / 128, MROWS / 128, 1), 256, GSMEM>>>(
        pAh, pAl, pWf, bo, bo, bo,
        nullptr, nullptr, nullptr, nullptr, out, 3);
}

// round 17
// speedup vs baseline: 7.7170x; 1.4175x over previous
#include <cuda_runtime.h>
#include <cuda_bf16.h>
#include <cuda_fp16.h>
#include <math.h>
#include <stdint.h>

#define BATCH  4
#define SEQ    2048
#define DMODEL 2048
#define NHEAD  16
#define HDIM   128
#define MROWS  (BATCH * SEQ)   // 8192
#define WSZ    ((size_t)DMODEL * DMODEL)

typedef __half f16;

// ---------------------------------------------------------------------------
// Scratch (device globals; no runtime allocation allowed)
// ---------------------------------------------------------------------------
__device__ f16 g_xf[(size_t)MROWS * DMODEL];   // x single fp16
__device__ f16 g_Wf[4 * WSZ];                  // 4 weight slots, single fp16
__device__ f16 g_Qh[(size_t)MROWS * DMODEL];   // Q hi/lo (exact vs fp32 Q)
__device__ f16 g_Ql[(size_t)MROWS * DMODEL];
__device__ f16 g_Kf[(size_t)MROWS * DMODEL];   // K single fp16
__device__ f16 g_Vf[(size_t)MROWS * DMODEL];   // V single fp16
__device__ f16 g_Af[(size_t)MROWS * DMODEL];   // attn out single fp16
__device__ uint32_t g_maskp[(size_t)BATCH * SEQ * (SEQ / 32)];

// ---------------------------------------------------------------------------
// Helpers
// ---------------------------------------------------------------------------
__device__ __forceinline__ void ldsm_x4(uint32_t r[4], const void* p) {
    uint32_t a = (uint32_t)__cvta_generic_to_shared(p);
    asm volatile("ldmatrix.sync.aligned.m8n8.x4.shared.b16 {%0,%1,%2,%3}, [%4];"
                 : "=r"(r[0]), "=r"(r[1]), "=r"(r[2]), "=r"(r[3]) : "r"(a));
}
__device__ __forceinline__ void ldsm_x4t(uint32_t r[4], const void* p) {
    uint32_t a = (uint32_t)__cvta_generic_to_shared(p);
    asm volatile("ldmatrix.sync.aligned.m8n8.x4.trans.shared.b16 {%0,%1,%2,%3}, [%4];"
                 : "=r"(r[0]), "=r"(r[1]), "=r"(r[2]), "=r"(r[3]) : "r"(a));
}
__device__ __forceinline__ void mma_f16(float c[4], const uint32_t a[4], const uint32_t b[2]) {
    asm volatile(
        "mma.sync.aligned.m16n8k16.row.col.f32.f16.f16.f32 "
        "{%0,%1,%2,%3}, {%4,%5,%6,%7}, {%8,%9}, {%0,%1,%2,%3};"
        : "+f"(c[0]), "+f"(c[1]), "+f"(c[2]), "+f"(c[3])
        : "r"(a[0]), "r"(a[1]), "r"(a[2]), "r"(a[3]), "r"(b[0]), "r"(b[1]));
}
__device__ __forceinline__ void cp16(void* s, const void* g) {
    uint32_t sa = (uint32_t)__cvta_generic_to_shared(s);
    asm volatile("cp.async.cg.shared.global [%0], [%1], 16;" :: "r"(sa), "l"(g));
}
__device__ __forceinline__ void cp_commit() { asm volatile("cp.async.commit_group;"); }

__device__ __forceinline__ uint32_t pack_f16x2(float lo, float hi) {
    __half2 h2 = __floats2half2_rn(lo, hi);
    return *(uint32_t*)&h2;
}

// ---------------------------------------------------------------------------
// Convert fp32 -> single fp16 (x)
// ---------------------------------------------------------------------------
__global__ __launch_bounds__(256) void conv_x(
    const float* __restrict__ in, f16* __restrict__ dst, int n4)
{
    int i = blockIdx.x * 256 + threadIdx.x;
    if (i >= n4) return;
    float4 f = ((const float4*)in)[i];
    ((__half2*)dst)[2 * i]     = __floats2half2_rn(f.x, f.y);
    ((__half2*)dst)[2 * i + 1] = __floats2half2_rn(f.z, f.w);
}

// ---------------------------------------------------------------------------
// Convert all 4 weights into single-fp16 slots. grid (WSZ/4/256, 4)
// ---------------------------------------------------------------------------
__global__ __launch_bounds__(256) void conv_w4(
    const float* __restrict__ w0, const float* __restrict__ w1,
    const float* __restrict__ w2, const float* __restrict__ w3,
    f16* __restrict__ dst)
{
    const int widx = blockIdx.y;
    const float* src = (widx == 0) ? w0 : (widx == 1) ? w1 : (widx == 2) ? w2 : w3;
    f16* dp = dst + (size_t)widx * WSZ;
    int i = blockIdx.x * 256 + threadIdx.x;
    float4 f = ((const float4*)src)[i];
    ((__half2*)dp)[2 * i]     = __floats2half2_rn(f.x, f.y);
    ((__half2*)dp)[2 * i + 1] = __floats2half2_rn(f.z, f.w);
}

// ---------------------------------------------------------------------------
// Pack int32 mask into bitfield
// ---------------------------------------------------------------------------
__global__ __launch_bounds__(256) void pack_mask(
    const int* __restrict__ mask, uint32_t* __restrict__ out, int nw)
{
    int i = blockIdx.x * 256 + threadIdx.x;
    if (i >= nw) return;
    const int4* p = (const int4*)mask + (size_t)i * 8;
    uint32_t w = 0;
    #pragma unroll
    for (int j = 0; j < 8; j++) {
        int4 v = p[j];
        w |= (v.x != 0 ? 1u : 0u) << (j * 4 + 0);
        w |= (v.y != 0 ? 1u : 0u) << (j * 4 + 1);
        w |= (v.z != 0 ? 1u : 0u) << (j * 4 + 2);
        w |= (v.w != 0 ? 1u : 0u) << (j * 4 + 3);
    }
    out[i] = w;
}

// ---------------------------------------------------------------------------
// GEMM fp16 1-term: C = A*W + bias (fp32 accum)
// A [M,K] single fp16, W [K,N] single fp16 (slot wslot0+z).
//   QKV fused: grid.z=3; z0 -> Q hi/lo, z1 -> K fp16, z2 -> V fp16.
//   O: grid.z=1, wslot0=3, Cf fp32.
// Tiles 128x128x64, 256 threads (8 warps, 32m x 64n), cp.async dbuf.
// ---------------------------------------------------------------------------
#define GBK 64
#define AP  72                           // halves pitch: 64 + 8
#define BP  136                          // halves pitch: 128 + 8
#define A_BUF (128 * AP * 2)             // 18432
#define B_BUF (GBK * BP * 2)             // 17408
#define GSTG  (A_BUF + B_BUF)            // 35840
#define GS_A(st) ((st) * GSTG)
#define GS_B(st) ((st) * GSTG + A_BUF)
#define GSMEM (2 * GSTG)                 // 71680

__global__ __launch_bounds__(256, 2) void gemm_f16(
    const f16* __restrict__ Ag,
    const f16* __restrict__ Wf4,
    const float* __restrict__ b0, const float* __restrict__ b1, const float* __restrict__ b2,
    f16* __restrict__ C0h, f16* __restrict__ C0l,
    f16* __restrict__ C1f, f16* __restrict__ C2f,
    float* __restrict__ Cf, int wslot0)
{
    extern __shared__ char sm[];
    const int z = blockIdx.z;
    const f16* Bg = Wf4 + (size_t)(wslot0 + z) * WSZ;
    const float* bias = (z == 0) ? b0 : (z == 1) ? b1 : b2;

    const int tid = threadIdx.x;
    const int l   = tid & 31;
    const int wid = tid >> 5;
    const int wm  = (wid & 3) * 32;
    const int wn  = (wid >> 2) * 64;
    const int m0  = blockIdx.y * 128;
    const int n0  = blockIdx.x * 128;
    const int K = DMODEL, N = DMODEL;

    float acc[2][8][4];
    #pragma unroll
    for (int mt = 0; mt < 2; mt++)
        #pragma unroll
        for (int nt = 0; nt < 8; nt++)
            #pragma unroll
            for (int q = 0; q < 4; q++) acc[mt][nt][q] = 0.f;

    auto issue = [&](int k0, int st) {
        char* pA = sm + GS_A(st);
        char* pB = sm + GS_B(st);
        // A tile: 128 rows x 64 halves = 8 chunks/row, 1024 chunks
        #pragma unroll
        for (int j = 0; j < 4; j++) {
            int u  = tid + j * 256;
            int r  = u >> 3;
            int c8 = (u & 7) * 8;
            cp16(pA + (r * AP + c8) * 2, Ag + (size_t)(m0 + r) * K + k0 + c8);
        }
        // B tile: 64 rows x 128 halves = 16 chunks/row, 1024 chunks
        #pragma unroll
        for (int j = 0; j < 4; j++) {
            int u   = tid + j * 256;
            int rb  = u >> 4;
            int cb8 = (u & 15) * 8;
            cp16(pB + (rb * BP + cb8) * 2, Bg + (size_t)(k0 + rb) * N + n0 + cb8);
        }
    };

    issue(0, 0); cp_commit();
    asm volatile("cp.async.wait_group 0;");
    __syncthreads();

    int st = 0;
    for (int k0 = 0; k0 < K; k0 += GBK) {
        const bool nxt = (k0 + GBK) < K;
        if (nxt) { issue(k0 + GBK, st ^ 1); cp_commit(); }

        char* pA = sm + GS_A(st);
        char* pB = sm + GS_B(st);

        #pragma unroll
        for (int ks = 0; ks < 4; ks++) {
            uint32_t ah[2][4];
            #pragma unroll
            for (int mt = 0; mt < 2; mt++) {
                int off = ((wm + mt * 16 + (l & 15)) * AP + ks * 16 + ((l & 16) >> 1)) * 2;
                ldsm_x4(ah[mt], pA + off);
            }
            uint32_t bb[4][4];
            #pragma unroll
            for (int q = 0; q < 4; q++) {
                int off = ((ks * 16 + (l & 15)) * BP + wn + q * 16 + ((l & 16) >> 1)) * 2;
                ldsm_x4t(bb[q], pB + off);
            }
            #pragma unroll
            for (int mt = 0; mt < 2; mt++)
                #pragma unroll
                for (int nt = 0; nt < 8; nt++) {
                    const uint32_t* bp = &bb[nt >> 1][(nt & 1) * 2];
                    mma_f16(acc[mt][nt], ah[mt], bp);
                }
        }
        if (nxt) asm volatile("cp.async.wait_group 0;");
        __syncthreads();
        st ^= 1;
    }

    #pragma unroll
    for (int mt = 0; mt < 2; mt++) {
        #pragma unroll
        for (int nt = 0; nt < 8; nt++) {
            int r0 = m0 + wm + mt * 16 + (l >> 2);
            int c  = n0 + wn + nt * 8 + (l & 3) * 2;
            float v[4];
            v[0] = acc[mt][nt][0] + bias[c];
            v[1] = acc[mt][nt][1] + bias[c + 1];
            v[2] = acc[mt][nt][2] + bias[c];
            v[3] = acc[mt][nt][3] + bias[c + 1];
            #pragma unroll
            for (int e = 0; e < 4; e++) {
                int row = r0 + (e >> 1) * 8;
                int col = c + (e & 1);
                size_t idx = (size_t)row * N + col;
                if (Cf) {
                    Cf[idx] = v[e];
                } else if (z == 0) {
                    f16 hh = __float2half_rn(v[e]);
                    C0h[idx] = hh;
                    C0l[idx] = __float2half_rn(v[e] - __half2float(hh));
                } else if (z == 1) {
                    C1f[idx] = __float2half_rn(v[e]);
                } else {
                    C2f[idx] = __float2half_rn(v[e]);
                }
            }
        }
    }
}

// ---------------------------------------------------------------------------
// Flash attention, register-resident FA2 (all fp16 mma).
// S = Qh*K + Ql*K (Q hi/lo exact, K single). P·V: P hi/lo + V single.
// Br=128, Bc=64, hd=128, 256 threads. Output: single fp16 [B,S,D].
// ---------------------------------------------------------------------------
#define FBR 128
#define FBC 64
#define FP  136
#define FQ_SZ (FBR * FP * 2)          // 34816
#define FKV_SZ (FBC * FP * 2)         // 17408
#define F_QH 0
#define F_QL (F_QH + FQ_SZ)
#define F_ST0 (F_QL + FQ_SZ)          // 69632
#define F_STG (2 * FKV_SZ)            // 34816 per stage (K, V)
#define F_K(st) (F_ST0 + (st) * F_STG)
#define F_V(st) (F_K(st) + FKV_SZ)
#define FSMEM (F_ST0 + 2 * F_STG)     // 139264

__global__ __launch_bounds__(256) void flash_f16(
    const f16* __restrict__ Qh, const f16* __restrict__ Ql,
    const f16* __restrict__ Kf, const f16* __restrict__ Vf,
    const uint32_t* __restrict__ maskp,
    f16* __restrict__ Of)
{
    extern __shared__ char sm[];
    const int tid = threadIdx.x;
    const int l   = tid & 31;
    const int wid = tid >> 5;
    const int g   = l >> 2;
    const int t   = l & 3;
    const int wm  = wid * 16;
    const int bh  = blockIdx.y;
    const int q0  = blockIdx.x * FBR;
    const int b   = bh >> 4;
    const int h   = bh & 15;
    const float NEG_INF = __int_as_float(0xff800000);
    const float SCALE = 0.08838834764831845f;

    // load Q tile (128 x 128 hi/lo)
    {
        const size_t qb = ((size_t)(b * SEQ + q0)) * DMODEL + (size_t)h * HDIM;
        #pragma unroll
        for (int j = 0; j < 8; j++) {
            int u = tid + j * 256;
            int r = u >> 4, c8 = (u & 15) * 8;
            size_t gp = qb + (size_t)r * DMODEL + c8;
            *(uint4*)(sm + F_QH + (r * FP + c8) * 2) = *(const uint4*)(Qh + gp);
            *(uint4*)(sm + F_QL + (r * FP + c8) * 2) = *(const uint4*)(Ql + gp);
        }
    }

    auto issue_kv = [&](int kt, int st) {
        const size_t kb = ((size_t)(b * SEQ + kt * FBC)) * DMODEL + (size_t)h * HDIM;
        char* KK = sm + F_K(st); char* VV = sm + F_V(st);
        #pragma unroll
        for (int j = 0; j < 4; j++) {
            int u = tid + j * 256;
            int r = u >> 4, c8 = (u & 15) * 8;
            size_t gp = kb + (size_t)r * DMODEL + c8;
            int so = (r * FP + c8) * 2;
            cp16(KK + so, Kf + gp);
            cp16(VV + so, Vf + gp);
        }
    };

    issue_kv(0, 0); cp_commit();
    issue_kv(1, 1); cp_commit();

    float m0r = NEG_INF, m1r = NEG_INF, l0r = 0.f, l1r = 0.f;
    float oacc[16][4];
    #pragma unroll
    for (int nt = 0; nt < 16; nt++)
        #pragma unroll
        for (int q = 0; q < 4; q++) oacc[nt][q] = 0.f;

    const int NT = SEQ / FBC;   // 32
    const size_t mrow0 = ((size_t)b * SEQ + q0 + wm + g) * (SEQ / 32);
    const size_t mrow1 = mrow0 + 8 * (SEQ / 32);

    for (int kt = 0; kt < NT; kt++) {
        asm volatile("cp.async.wait_group 1;");
        __syncthreads();
        const int st = kt & 1;
        const char* KK = sm + F_K(st);
        const char* VV = sm + F_V(st);

        const uint32_t w00 = maskp[mrow0 + kt * 2];
        const uint32_t w01 = maskp[mrow0 + kt * 2 + 1];
        const uint32_t w10 = maskp[mrow1 + kt * 2];
        const uint32_t w11 = maskp[mrow1 + kt * 2 + 1];

        // ---- S = Q K^T (fp16 2-term), warp tile 16m x 64n ----
        float sacc[8][4];
        #pragma unroll
        for (int nt = 0; nt < 8; nt++)
            #pragma unroll
            for (int q = 0; q < 4; q++) sacc[nt][q] = 0.f;

        #pragma unroll
        for (int ks = 0; ks < 8; ks++) {
            uint32_t qh4[4], ql4[4];
            int qoff = ((wm + (l & 15)) * FP + ks * 16 + ((l & 16) >> 1)) * 2;
            ldsm_x4(qh4, sm + F_QH + qoff);
            ldsm_x4(ql4, sm + F_QL + qoff);
            #pragma unroll
            for (int q = 0; q < 4; q++) {
                uint32_t kk4[4];
                int nr = q * 16 + (l & 7) + ((l & 16) >> 1);
                int kc = ks * 16 + (l & 8);
                ldsm_x4(kk4, KK + (nr * FP + kc) * 2);
                #pragma unroll
                for (int half = 0; half < 2; half++) {
                    const uint32_t* bp = &kk4[half * 2];
                    float* s = sacc[q * 2 + half];
                    mma_f16(s, qh4, bp);
                    mma_f16(s, ql4, bp);
                }
            }
        }

        // ---- scale + mask + row max ----
        float mx0 = NEG_INF, mx1 = NEG_INF;
        #pragma unroll
        for (int nt = 0; nt < 8; nt++) {
            const int c  = nt * 8 + 2 * t;
            const int sh = c & 31;
            const uint32_t wr0 = (nt < 4) ? w00 : w01;
            const uint32_t wr1 = (nt < 4) ? w10 : w11;
            float v0 = sacc[nt][0] * SCALE; if (!((wr0 >> sh) & 1))       v0 = NEG_INF;
            float v1 = sacc[nt][1] * SCALE; if (!((wr0 >> (sh + 1)) & 1)) v1 = NEG_INF;
            float v2 = sacc[nt][2] * SCALE; if (!((wr1 >> sh) & 1))       v2 = NEG_INF;
            float v3 = sacc[nt][3] * SCALE; if (!((wr1 >> (sh + 1)) & 1)) v3 = NEG_INF;
            sacc[nt][0] = v0; sacc[nt][1] = v1; sacc[nt][2] = v2; sacc[nt][3] = v3;
            mx0 = fmaxf(mx0, fmaxf(v0, v1));
            mx1 = fmaxf(mx1, fmaxf(v2, v3));
        }
        mx0 = fmaxf(mx0, __shfl_xor_sync(0xffffffffu, mx0, 1));
        mx0 = fmaxf(mx0, __shfl_xor_sync(0xffffffffu, mx0, 2));
        mx1 = fmaxf(mx1, __shfl_xor_sync(0xffffffffu, mx1, 1));
        mx1 = fmaxf(mx1, __shfl_xor_sync(0xffffffffu, mx1, 2));

        const float mn0 = fmaxf(m0r, mx0);
        const float mn1 = fmaxf(m1r, mx1);
        const float al0 = (m0r == NEG_INF) ? 0.f : __expf(m0r - mn0);
        const float al1 = (m1r == NEG_INF) ? 0.f : __expf(m1r - mn1);
        m0r = mn0; m1r = mn1;

        // ---- P = exp(S - m), rowsum ----
        float sum0 = 0.f, sum1 = 0.f;
        #pragma unroll
        for (int nt = 0; nt < 8; nt++) {
            float p0 = __expf(sacc[nt][0] - mn0);
            float p1 = __expf(sacc[nt][1] - mn0);
            float p2 = __expf(sacc[nt][2] - mn1);
            float p3 = __expf(sacc[nt][3] - mn1);
            sacc[nt][0] = p0; sacc[nt][1] = p1; sacc[nt][2] = p2; sacc[nt][3] = p3;
            sum0 += p0 + p1;
            sum1 += p2 + p3;
        }
        sum0 += __shfl_xor_sync(0xffffffffu, sum0, 1);
        sum0 += __shfl_xor_sync(0xffffffffu, sum0, 2);
        sum1 += __shfl_xor_sync(0xffffffffu, sum1, 1);
        sum1 += __shfl_xor_sync(0xffffffffu, sum1, 2);
        l0r = l0r * al0 + sum0;
        l1r = l1r * al1 + sum1;

        // ---- rescale O (skip when alpha == 1 exactly) ----
        if (!(al0 == 1.f && al1 == 1.f)) {
            #pragma unroll
            for (int nt = 0; nt < 16; nt++) {
                oacc[nt][0] *= al0; oacc[nt][1] *= al0;
                oacc[nt][2] *= al1; oacc[nt][3] *= al1;
            }
        }

        // ---- O += P V : P hi/lo fp16, V single fp16 ----
        #pragma unroll
        for (int s = 0; s < 4; s++) {
            uint32_t pah[4], pal[4];
            {
                const float* c0 = sacc[2 * s];
                const float* c1 = sacc[2 * s + 1];
                pah[0] = pack_f16x2(c0[0], c0[1]);
                pah[1] = pack_f16x2(c0[2], c0[3]);
                pah[2] = pack_f16x2(c1[0], c1[1]);
                pah[3] = pack_f16x2(c1[2], c1[3]);
                __half2 h2;
                h2 = *(__half2*)&pah[0];
                pal[0] = pack_f16x2(c0[0] - __half2float(h2.x), c0[1] - __half2float(h2.y));
                h2 = *(__half2*)&pah[1];
                pal[1] = pack_f16x2(c0[2] - __half2float(h2.x), c0[3] - __half2float(h2.y));
                h2 = *(__half2*)&pah[2];
                pal[2] = pack_f16x2(c1[0] - __half2float(h2.x), c1[1] - __half2float(h2.y));
                h2 = *(__half2*)&pah[3];
                pal[3] = pack_f16x2(c1[2] - __half2float(h2.x), c1[3] - __half2float(h2.y));
            }
            #pragma unroll
            for (int q = 0; q < 8; q++) {
                uint32_t vh4[4];
                int vr = s * 16 + (l & 15);
                int vc = q * 16 + ((l & 16) >> 1);
                ldsm_x4t(vh4, VV + (vr * FP + vc) * 2);
                #pragma unroll
                for (int half = 0; half < 2; half++) {
                    const uint32_t* bp = &vh4[half * 2];
                    float* o = oacc[q * 2 + half];
                    mma_f16(o, pah, bp);
                    mma_f16(o, pal, bp);
                }
            }
        }

        __syncthreads();
        if (kt + 2 < NT) issue_kv(kt + 2, st);
        cp_commit();
    }

    // ---- epilogue: normalize, write single fp16 to [B,S,D] ----
    {
        const float inv0 = 1.f / l0r;
        const float inv1 = 1.f / l1r;
        const int r0 = q0 + wm + g;
        const int r1 = r0 + 8;
        const size_t b0 = ((size_t)(b * SEQ + r0)) * DMODEL + (size_t)h * HDIM;
        const size_t b1 = ((size_t)(b * SEQ + r1)) * DMODEL + (size_t)h * HDIM;
        #pragma unroll
        for (int nt = 0; nt < 16; nt++) {
            const int c = nt * 8 + 2 * t;
            *(uint32_t*)(Of + b0 + c) = pack_f16x2(oacc[nt][0] * inv0, oacc[nt][1] * inv0);
            *(uint32_t*)(Of + b1 + c) = pack_f16x2(oacc[nt][2] * inv1, oacc[nt][3] * inv1);
        }
    }
}

// ---------------------------------------------------------------------------
// Launch
// ---------------------------------------------------------------------------
extern "C" void kernel_launch(void* const* d_in, const int* in_sizes, int n_in,
                              void* d_out, int out_size)
{
    const float* x    = (const float*)d_in[0];
    const int*   mask = (const int*)  d_in[1];
    const float* Wq   = (const float*)d_in[2];
    const float* bq   = (const float*)d_in[3];
    const float* Wk   = (const float*)d_in[4];
    const float* bk   = (const float*)d_in[5];
    const float* Wv   = (const float*)d_in[6];
    const float* bv   = (const float*)d_in[7];
    const float* Wo   = (const float*)d_in[8];
    const float* bo   = (const float*)d_in[9];
    float* out = (float*)d_out;

    f16 *pxf, *pWf, *pQh, *pQl, *pKf, *pVf, *pAf;
    uint32_t* pMp;
    cudaGetSymbolAddress((void**)&pxf, g_xf);
    cudaGetSymbolAddress((void**)&pWf, g_Wf);
    cudaGetSymbolAddress((void**)&pQh, g_Qh);
    cudaGetSymbolAddress((void**)&pQl, g_Ql);
    cudaGetSymbolAddress((void**)&pKf, g_Kf);
    cudaGetSymbolAddress((void**)&pVf, g_Vf);
    cudaGetSymbolAddress((void**)&pAf, g_Af);
    cudaGetSymbolAddress((void**)&pMp, g_maskp);

    cudaFuncSetAttribute(gemm_f16, cudaFuncAttributeMaxDynamicSharedMemorySize, GSMEM);
    cudaFuncSetAttribute(flash_f16, cudaFuncAttributeMaxDynamicSharedMemorySize, FSMEM);

    const int n4x = MROWS * DMODEL / 4;
    const int n4w = (int)(WSZ / 4);
    const int nw  = BATCH * SEQ * (SEQ / 32);

    conv_x<<<(n4x + 255) / 256, 256>>>(x, pxf, n4x);
    pack_mask<<<(nw + 255) / 256, 256>>>(mask, pMp, nw);
    conv_w4<<<dim3(n4w / 256, 4), 256>>>(Wq, Wk, Wv, Wo, pWf);

    // Fused Q/K/V projection (1-term A, fp16)
    gemm_f16<<<dim3(DMODEL / 128, MROWS / 128, 3), 256, GSMEM>>>(
        pxf, pWf, bq, bk, bv,
        pQh, pQl, pKf, pVf, nullptr, 0);

    flash_f16<<<dim3(SEQ / FBR, BATCH * NHEAD), 256, FSMEM>>>(
        pQh, pQl, pKf, pVf, pMp, pAf);

    // Output projection (weight slot 3, fp32 out)
    gemm_f16<<<dim3(DMODEL / 128, MROWS / 128, 1), 256, GSMEM>>>(
        pAf, pWf, bo, bo, bo,
        nullptr, nullptr, nullptr, nullptr, out, 3);
}